// round 9
// baseline (speedup 1.0000x reference)
#include <cuda_runtime.h>
#include <math.h>

#define B 8
#define SL 4096
#define D 128
#define NH 8
#define NB 64       // buckets per hash
#define NC 512      // n_chunks = NH * NB
#define BS 64       // bucket/chunk size
#define NSL (NH*SL) // 32768
#define PAD 132     // smem row stride (floats); %32==4 -> conflict-free rows & cols

#define MNEG (-3.402823466e38f)

typedef unsigned long long ull;

// packed 2x fp32 fma (Blackwell f32x2 pipe; PTX-only)
__device__ __forceinline__ void fma2(ull& d, ull a, ull b) {
    asm("fma.rn.f32x2 %0, %1, %2, %0;" : "+l"(d) : "l"(a), "l"(b));
}
__device__ __forceinline__ ull pack2(float lo, float hi) {
    ull r; asm("mov.b64 %0, {%1, %2};" : "=l"(r) : "f"(lo), "f"(hi)); return r;
}
__device__ __forceinline__ float2 unpack2(ull v) {
    float2 r; asm("mov.b64 {%0, %1}, %2;" : "=f"(r.x), "=f"(r.y) : "l"(v)); return r;
}

// ---------------- scratch (device globals; no runtime allocation) ----------
__device__ int   g_buckets[B][NH][SL];   // bucket incl. h*NB offset
__device__ int   g_hist[B][NC];
__device__ int   g_boff[B][NC];
__device__ int   g_sticker[B][NSL];      // sorted tickers
__device__ int   g_undo[B][NSL];         // ticker -> sorted pos
__device__ int   g_loc1[B][NH][SL];
__device__ int   g_loc2[B][NH][SL];
__device__ float g_so[B][NSL][D];        // sorted attention output
__device__ float g_slog[B][NSL];         // sorted lse

// ---------------- kernels --------------------------------------------------
__global__ void k_zero_hist() {
    g_hist[blockIdx.x][threadIdx.x] = 0;
}

// buckets + histogram. grid (SL/256, NH, B), block 256.
__global__ void k_buckets(const float* __restrict__ qk, const float* __restrict__ rot) {
    __shared__ float rs[32 * 32];      // d-tile (32) x n (32)
    __shared__ float qt_[256 * 33];    // tokens x d-tile, stride 33
    int b = blockIdx.z, h = blockIdx.y;
    int tid = threadIdx.x;
    int s0 = blockIdx.x * 256;

    ull acc2[16];
#pragma unroll
    for (int n = 0; n < 16; n++) acc2[n] = 0ull;

    for (int d0 = 0; d0 < 128; d0 += 32) {
        for (int i = tid; i < 32 * 32; i += 256) {
            int dd = i >> 5, nn = i & 31;
            rs[i] = rot[((size_t)(d0 + dd) * NH + h) * 32 + nn];
        }
        for (int i = tid; i < 256 * 32; i += 256) {
            int r = i >> 5, c = i & 31;
            qt_[r * 33 + c] = qk[((size_t)b * SL + s0 + r) * D + d0 + c];
        }
        __syncthreads();
#pragma unroll 4
        for (int dd = 0; dd < 32; dd++) {
            float qv = qt_[tid * 33 + dd];
            ull qq = pack2(qv, qv);
            const ull* r2 = (const ull*)&rs[dd * 32];
#pragma unroll
            for (int n = 0; n < 16; n++) fma2(acc2[n], qq, r2[n]);
        }
        __syncthreads();
    }
    float acc[32];
#pragma unroll
    for (int n = 0; n < 16; n++) {
        float2 p = unpack2(acc2[n]);
        acc[2 * n] = p.x; acc[2 * n + 1] = p.y;
    }
    // argmax over [acc, -acc], first-max-wins (matches jnp.argmax)
    float best = acc[0]; int idx = 0;
#pragma unroll
    for (int n = 1; n < 32; n++) if (acc[n] > best) { best = acc[n]; idx = n; }
#pragma unroll
    for (int n = 0; n < 32; n++) if (-acc[n] > best) { best = -acc[n]; idx = 32 + n; }
    int s = s0 + tid;
    int bucket = idx + h * NB;
    g_buckets[b][h][s] = bucket;
    atomicAdd(&g_hist[b][bucket], 1);
}

// exclusive scan of 512 bins per batch. grid B, block NC. Hillis-Steele.
__global__ void k_prefix() {
    __shared__ int sh[NC];
    int b = blockIdx.x, tid = threadIdx.x;
    int v = g_hist[b][tid];
    sh[tid] = v;
    __syncthreads();
#pragma unroll
    for (int off = 1; off < NC; off <<= 1) {
        int x = (tid >= off) ? sh[tid - off] : 0;
        __syncthreads();
        sh[tid] += x;
        __syncthreads();
    }
    g_boff[b][tid] = sh[tid] - v;   // exclusive
}

// stable counting-sort scatter: 4 warps per bucket, two-pass (count, scatter).
// grid (NC, B), block 128
__global__ void k_scatter() {
    int bk = blockIdx.x, b = blockIdx.y;
    int h = bk >> 6;
    int warp = threadIdx.x >> 5, lane = threadIdx.x & 31;
    const int* bb = &g_buckets[b][h][0];
    int t0 = warp * (SL / 4);

    __shared__ int wc[4];
    int cnt = 0;
    for (int base = 0; base < SL / 4; base += 32) {
        bool m = (bb[t0 + base + lane] == bk);
        cnt += __popc(__ballot_sync(0xffffffffu, m));
    }
    if (lane == 0) wc[warp] = cnt;
    __syncthreads();

    int pos = g_boff[b][bk];
#pragma unroll
    for (int w = 0; w < 4; w++) if (w < warp) pos += wc[w];

    for (int base = 0; base < SL / 4; base += 32) {
        int t = t0 + base + lane;
        bool m = (bb[t] == bk);
        unsigned bal = __ballot_sync(0xffffffffu, m);
        if (m) {
            int r = __popc(bal & ((1u << lane) - 1));
            int j = h * SL + t;
            g_sticker[b][pos + r] = j;
            g_undo[b][j] = pos + r;
        }
        pos += __popc(bal);
    }
}

// duplicate-detection location codes. grid (B*NSL/256), block 256
__global__ void k_loc() {
    int idx = blockIdx.x * 256 + threadIdx.x;
    int b = idx / NSL, r = idx % NSL;
    int h = r >> 12, t = r & (SL - 1);
    int chunk = g_undo[b][r] >> 6;
    int bucket = g_buckets[b][h][t];
    g_loc1[b][h][t] = bucket * NC + chunk;
    g_loc2[b][h][t] = bucket * NC + ((chunk + 1) & (NC - 1));
}

// chunked attention. grid (NC, B), block 512, dynamic smem, 2 blocks/SM.
// 16 warps; QK: warp w owns query rows {w, w+16, w+32, w+48}.
// One 128-row buffer holds K during QK, then V during PV (re-gathered).
// PV: warp pair (2u,2u+1) owns rows {u, u+8, ..., u+56}; warp 2u d[0:64), 2u+1 d[64:128).
extern __shared__ float smem[];
__global__ void __launch_bounds__(512, 2)
k_attn(const float* __restrict__ qk, const float* __restrict__ v) {
    int n = blockIdx.x, b = blockIdx.y;
    int tid = threadIdx.x;
    int warp = tid >> 5, lane = tid & 31;

    float* qs = smem;              // 64*PAD  (q rows; reused as probs)
    float* kv = qs + 64 * PAD;     // 128*PAD (K in phase 1, V in phase 2)
    int* qt = (int*)(kv + 128 * PAD); // 64
    int* qb = qt + 64;                // 64
    int* kt = qb + 64;                // 128
    int* kb = kt + 128;               // 128
    int* ql1 = kb + 128;              // 64*8
    int* kl  = ql1 + 512;             // 128*18 (loc1/loc2 interleaved pairs)

    int prev = (n + NC - 1) & (NC - 1);

    // ---- batched index loads first (full MLP on the dependent gathers) ----
    int tfk[8], tfq[4];
#pragma unroll
    for (int u = 0; u < 8; u++) {
        int z = warp + 16 * u;
        int p = (z < 64) ? (n * BS + z) : (prev * BS + (z - 64));
        tfk[u] = g_sticker[b][p];
    }
#pragma unroll
    for (int u = 0; u < 4; u++)
        tfq[u] = g_sticker[b][n * BS + warp + 16 * u];

    // ---- K rows (z<64 current chunk, z>=64 previous chunk) ----
#pragma unroll
    for (int u = 0; u < 8; u++) {
        int z = warp + 16 * u;
        int t = tfk[u] & (SL - 1), h = tfk[u] >> 12;
        const float* src = qk + ((size_t)b * SL + t) * D;
        float4 x = ((const float4*)src)[lane];
        float ss = x.x * x.x + x.y * x.y + x.z * x.z + x.w * x.w;
#pragma unroll
        for (int o = 16; o > 0; o >>= 1) ss += __shfl_xor_sync(0xffffffffu, ss, o);
        float inv = rsqrtf(fmaxf(ss, 1e-24f));
        ((float4*)(kv + z * PAD))[lane] = make_float4(x.x * inv, x.y * inv, x.z * inv, x.w * inv);
        if (lane == 0) { kt[z] = t; kb[z] = g_buckets[b][h][t]; }
        if (lane < 8)       kl[z * 18 + 2 * lane]           = g_loc1[b][lane][t];
        else if (lane < 16) kl[z * 18 + 2 * (lane - 8) + 1] = g_loc2[b][lane - 8][t];
    }
    // ---- q rows ----
#pragma unroll
    for (int u = 0; u < 4; u++) {
        int s = warp + 16 * u;
        int t = tfq[u] & (SL - 1), h = tfq[u] >> 12;
        ((float4*)(qs + s * PAD))[lane] = ((const float4*)(qk + ((size_t)b * SL + t) * D))[lane];
        if (lane == 0) { qt[s] = t; qb[s] = g_buckets[b][h][t]; }
        if (lane < 8) ql1[s * 8 + lane] = g_loc1[b][lane][t];
    }
    __syncthreads();

    // ---- QK^T: 4 rows x 4 z tile, packed f32x2 over even/odd d ----
    ull acc2[4][4];
#pragma unroll
    for (int j = 0; j < 4; j++)
#pragma unroll
        for (int i = 0; i < 4; i++) acc2[j][i] = 0ull;

#pragma unroll 2
    for (int d = 0; d < 128; d += 4) {
        ulonglong2 kx[4];
#pragma unroll
        for (int i = 0; i < 4; i++)
            kx[i] = *(const ulonglong2*)(kv + (lane + 32 * i) * PAD + d);
#pragma unroll
        for (int j = 0; j < 4; j++) {
            ulonglong2 q2 = *(const ulonglong2*)(qs + (warp + 16 * j) * PAD + d);  // broadcast
#pragma unroll
            for (int i = 0; i < 4; i++) {
                fma2(acc2[j][i], q2.x, kx[i].x);
                fma2(acc2[j][i], q2.y, kx[i].y);
            }
        }
    }
    float acc[4][4];
#pragma unroll
    for (int j = 0; j < 4; j++)
#pragma unroll
        for (int i = 0; i < 4; i++) {
            float2 p = unpack2(acc2[j][i]);
            acc[j][i] = p.x + p.y;
        }

    // ---- masks + dup correction (reference order: causal, self, bucket, dup) ----
    const float scale = 0.08838834764831845f;  // 128^-0.5
#pragma unroll
    for (int j = 0; j < 4; j++) {
        int s = warp + 16 * j;
        int qtv = qt[s], qbv = qb[s];
        int ql[8];
#pragma unroll
        for (int m = 0; m < 8; m++) ql[m] = ql1[s * 8 + m];
#pragma unroll
        for (int i = 0; i < 4; i++) {
            int z = lane + 32 * i;
            float val = acc[j][i] * scale;
            int ktv = kt[z];
            if (qtv < ktv)  val = MNEG;
            if (qtv == ktv) val = -10000.f;
            if (qbv != kb[z]) val = MNEG;
            int cnt = 0;
#pragma unroll
            for (int m = 0; m < 8; m++) {
                int2 lp = *(const int2*)&kl[z * 18 + 2 * m];
                cnt += (ql[m] == lp.x) + (ql[m] == lp.y);
            }
            val -= __logf((float)cnt + 1e-9f);
            acc[j][i] = val;
        }
    }

    // ---- per-row softmax via warp shuffles; probs overwrite own qs rows ----
#pragma unroll
    for (int j = 0; j < 4; j++) {
        float m = fmaxf(fmaxf(acc[j][0], acc[j][1]), fmaxf(acc[j][2], acc[j][3]));
#pragma unroll
        for (int o = 16; o > 0; o >>= 1) m = fmaxf(m, __shfl_xor_sync(0xffffffffu, m, o));
        float e[4]; float sum = 0.f;
#pragma unroll
        for (int i = 0; i < 4; i++) { e[i] = __expf(acc[j][i] - m); sum += e[i]; }
#pragma unroll
        for (int o = 16; o > 0; o >>= 1) sum += __shfl_xor_sync(0xffffffffu, sum, o);
        int s = warp + 16 * j;
        if (lane == 0) g_slog[b][n * BS + s] = m + __logf(sum);
        float inv = 1.f / sum;
#pragma unroll
        for (int i = 0; i < 4; i++) qs[s * PAD + lane + 32 * i] = e[i] * inv;
    }
    __syncthreads();   // all warps done reading K; probs now block-visible

    // ---- phase 2: gather V into the shared buffer ----
#pragma unroll
    for (int u = 0; u < 8; u++) {
        int z = warp + 16 * u;
        int p = (z < 64) ? (n * BS + z) : (prev * BS + (z - 64));
        int t = g_sticker[b][p] & (SL - 1);
        ((float4*)(kv + z * PAD))[lane] = ((const float4*)(v + ((size_t)b * SL + t) * D))[lane];
    }
    __syncthreads();

    // ---- PV: warp pair splits d; 8 rows x 2 d-cols (f32x2) per thread ----
    int prow0 = warp >> 1;                 // pair id: rows prow0 + 8*k
    int dd2 = (warp & 1) * 64 + lane * 2;  // this warp's d-half
    ull o2[8];
#pragma unroll
    for (int k = 0; k < 8; k++) o2[k] = 0ull;

#pragma unroll 2
    for (int z0 = 0; z0 < 128; z0 += 4) {
        ull vv0 = *(const ull*)(kv + (z0 + 0) * PAD + dd2);
        ull vv1 = *(const ull*)(kv + (z0 + 1) * PAD + dd2);
        ull vv2 = *(const ull*)(kv + (z0 + 2) * PAD + dd2);
        ull vv3 = *(const ull*)(kv + (z0 + 3) * PAD + dd2);
#pragma unroll
        for (int k = 0; k < 8; k++) {
            float4 p4 = *(const float4*)(qs + (prow0 + 8 * k) * PAD + z0);  // broadcast
            fma2(o2[k], pack2(p4.x, p4.x), vv0);
            fma2(o2[k], pack2(p4.y, p4.y), vv1);
            fma2(o2[k], pack2(p4.z, p4.z), vv2);
            fma2(o2[k], pack2(p4.w, p4.w), vv3);
        }
    }
#pragma unroll
    for (int k = 0; k < 8; k++) {
        int s = prow0 + 8 * k;
        float2 a = unpack2(o2[k]);
        *(float2*)(&g_so[b][n * BS + s][dd2]) = a;
    }
}

// cross-hash-round combine. grid (SL, B), block 128 (one thread per dim)
__global__ void k_combine(float* __restrict__ out) {
    int t = blockIdx.x, b = blockIdx.y;
    int d = threadIdx.x;
    int p[NH];
    float l[NH];
    float m = MNEG;
#pragma unroll
    for (int h = 0; h < NH; h++) {
        p[h] = g_undo[b][h * SL + t];
        l[h] = g_slog[b][p[h]];
        m = fmaxf(m, l[h]);
    }
    float sum = 0.f;
#pragma unroll
    for (int h = 0; h < NH; h++) { l[h] = __expf(l[h] - m); sum += l[h]; }
    float inv = 1.f / sum;
    float acc = 0.f;
#pragma unroll
    for (int h = 0; h < NH; h++) acc += l[h] * inv * g_so[b][p[h]][d];
    out[((size_t)b * SL + t) * D + d] = acc;
}

// ---------------- launch ----------------------------------------------------
extern "C" void kernel_launch(void* const* d_in, const int* in_sizes, int n_in,
                              void* d_out, int out_size) {
    (void)in_sizes; (void)n_in; (void)out_size;
    const float* qk  = (const float*)d_in[0];
    const float* v   = (const float*)d_in[1];
    const float* rot = (const float*)d_in[2];
    float* out = (float*)d_out;

    // floats: (64+128)*PAD ; ints: 64+64+128+128+512+128*18 = 3200
    const int smem_bytes = (192 * PAD) * 4 + 3200 * 4;  // 114,176 B -> 2 blocks/SM
    cudaFuncSetAttribute(k_attn, cudaFuncAttributeMaxDynamicSharedMemorySize, smem_bytes);

    k_zero_hist<<<B, NC>>>();
    k_buckets<<<dim3(SL / 256, NH, B), 256>>>(qk, rot);
    k_prefix<<<B, NC>>>();
    k_scatter<<<dim3(NC, B), 128>>>();
    k_loc<<<(B * NSL) / 256, 256>>>();
    k_attn<<<dim3(NC, B), 512, smem_bytes>>>(qk, v);
    k_combine<<<dim3(SL, B), 128>>>(out);
}

// round 12
// speedup vs baseline: 1.5561x; 1.5561x over previous
#include <cuda_runtime.h>
#include <cuda_fp16.h>
#include <stdint.h>
#include <math.h>

#define B 8
#define SL 4096
#define D 128
#define NH 8
#define NB 64
#define NC 512
#define BS 64
#define NSL (NH*SL)
#define MNEG (-3.402823466e38f)

typedef unsigned long long ull;

__device__ __forceinline__ void fma2(ull& d, ull a, ull b) {
    asm("fma.rn.f32x2 %0, %1, %2, %0;" : "+l"(d) : "l"(a), "l"(b));
}
__device__ __forceinline__ ull pack2(float lo, float hi) {
    ull r; asm("mov.b64 %0, {%1, %2};" : "=l"(r) : "f"(lo), "f"(hi)); return r;
}
__device__ __forceinline__ float2 unpack2(ull v) {
    float2 r; asm("mov.b64 {%0, %1}, %2;" : "=f"(r.x), "=f"(r.y) : "l"(v)); return r;
}
__device__ __forceinline__ uint32_t smem_u32(const void* p) {
    uint32_t a;
    asm("{ .reg .u64 t; cvta.to.shared.u64 t, %1; cvt.u32.u64 %0, t; }" : "=r"(a) : "l"(p));
    return a;
}

// ---- warp-level tensor core primitives (portable PTX, HMMA pipe) ----
#define LDSM_X4(r0, r1, r2, r3, a) \
    asm volatile("ldmatrix.sync.aligned.m8n8.x4.shared.b16 {%0,%1,%2,%3}, [%4];" \
        : "=r"(r0), "=r"(r1), "=r"(r2), "=r"(r3) : "r"(a))
#define LDSM_X2(r0, r1, a) \
    asm volatile("ldmatrix.sync.aligned.m8n8.x2.shared.b16 {%0,%1}, [%2];" \
        : "=r"(r0), "=r"(r1) : "r"(a))
#define LDSM_X2T(r0, r1, a) \
    asm volatile("ldmatrix.sync.aligned.m8n8.x2.trans.shared.b16 {%0,%1}, [%2];" \
        : "=r"(r0), "=r"(r1) : "r"(a))
#define MMA16816(c, a0, a1, a2, a3, b0, b1) \
    asm volatile("mma.sync.aligned.m16n8k16.row.col.f32.f16.f16.f32 " \
        "{%0,%1,%2,%3}, {%4,%5,%6,%7}, {%8,%9}, {%0,%1,%2,%3};" \
        : "+f"((c)[0]), "+f"((c)[1]), "+f"((c)[2]), "+f"((c)[3]) \
        : "r"(a0), "r"(a1), "r"(a2), "r"(a3), "r"(b0), "r"(b1))

// ---- k_attn smem layout (bytes). fp16 rows, stride 136 halves = 272 B ----
#define RSB 272
#define QHOFF 0         // Q fp16 64 rows; reused as P fp16
#define KHOFF 17408     // K fp16 128 rows (normalized)
#define VHOFF 52224     // V fp16 128 rows
#define IOFF  87040     // ints: qt64 qb64 kt128 kb128 ql1[512] kl[2048]
#define RMAXOFF 98816   // float[64*4]
#define RSUMOFF 99840   // float[64*4]
#define SMEM_ATTN 100864

// ---------------- scratch ----------------------------------------------------
__device__ int   g_buckets[B][NH][SL];
__device__ int   g_hist[B][NC];
__device__ int   g_boff[B][NC];
__device__ int   g_sticker[B][NSL];
__device__ int   g_undo[B][NSL];
__device__ int   g_loc1[B][NH][SL];
__device__ int   g_loc2[B][NH][SL];
__device__ float g_so[B][NSL][D];
__device__ float g_slog[B][NSL];

__global__ void k_zero_hist() { g_hist[blockIdx.x][threadIdx.x] = 0; }

__global__ void k_buckets(const float* __restrict__ qk, const float* __restrict__ rot) {
    __shared__ float rs[32 * 32];
    __shared__ float qt_[256 * 33];
    int b = blockIdx.z, h = blockIdx.y, tid = threadIdx.x;
    int s0 = blockIdx.x * 256;
    ull acc2[16];
#pragma unroll
    for (int n = 0; n < 16; n++) acc2[n] = 0ull;
    for (int d0 = 0; d0 < 128; d0 += 32) {
        for (int i = tid; i < 32 * 32; i += 256) {
            int dd = i >> 5, nn = i & 31;
            rs[i] = rot[((size_t)(d0 + dd) * NH + h) * 32 + nn];
        }
        for (int i = tid; i < 256 * 32; i += 256) {
            int r = i >> 5, c = i & 31;
            qt_[r * 33 + c] = qk[((size_t)b * SL + s0 + r) * D + d0 + c];
        }
        __syncthreads();
#pragma unroll 4
        for (int dd = 0; dd < 32; dd++) {
            float qv = qt_[tid * 33 + dd];
            ull qq = pack2(qv, qv);
            const ull* r2 = (const ull*)&rs[dd * 32];
#pragma unroll
            for (int n = 0; n < 16; n++) fma2(acc2[n], qq, r2[n]);
        }
        __syncthreads();
    }
    float acc[32];
#pragma unroll
    for (int n = 0; n < 16; n++) { float2 p = unpack2(acc2[n]); acc[2*n] = p.x; acc[2*n+1] = p.y; }
    float best = acc[0]; int idx = 0;
#pragma unroll
    for (int n = 1; n < 32; n++) if (acc[n] > best) { best = acc[n]; idx = n; }
#pragma unroll
    for (int n = 0; n < 32; n++) if (-acc[n] > best) { best = -acc[n]; idx = 32 + n; }
    int bucket = idx + h * NB;
    g_buckets[b][h][s0 + tid] = bucket;
    atomicAdd(&g_hist[b][bucket], 1);
}

__global__ void k_prefix() {
    __shared__ int sh[NC];
    int b = blockIdx.x, tid = threadIdx.x;
    int v = g_hist[b][tid];
    sh[tid] = v;
    __syncthreads();
#pragma unroll
    for (int off = 1; off < NC; off <<= 1) {
        int x = (tid >= off) ? sh[tid - off] : 0;
        __syncthreads();
        sh[tid] += x;
        __syncthreads();
    }
    g_boff[b][tid] = sh[tid] - v;
}

__global__ void k_scatter() {
    int bk = blockIdx.x, b = blockIdx.y;
    int h = bk >> 6;
    int warp = threadIdx.x >> 5, lane = threadIdx.x & 31;
    const int* bb = &g_buckets[b][h][0];
    int t0 = warp * (SL / 4);
    __shared__ int wc[4];
    int cnt = 0;
    for (int base = 0; base < SL / 4; base += 32) {
        bool m = (bb[t0 + base + lane] == bk);
        cnt += __popc(__ballot_sync(0xffffffffu, m));
    }
    if (lane == 0) wc[warp] = cnt;
    __syncthreads();
    int pos = g_boff[b][bk];
#pragma unroll
    for (int w = 0; w < 4; w++) if (w < warp) pos += wc[w];
    for (int base = 0; base < SL / 4; base += 32) {
        int t = t0 + base + lane;
        bool m = (bb[t] == bk);
        unsigned bal = __ballot_sync(0xffffffffu, m);
        if (m) {
            int r = __popc(bal & ((1u << lane) - 1));
            int j = h * SL + t;
            g_sticker[b][pos + r] = j;
            g_undo[b][j] = pos + r;
        }
        pos += __popc(bal);
    }
}

__global__ void k_loc() {
    int idx = blockIdx.x * 256 + threadIdx.x;
    int b = idx / NSL, r = idx % NSL;
    int h = r >> 12, t = r & (SL - 1);
    int chunk = g_undo[b][r] >> 6;
    int bucket = g_buckets[b][h][t];
    g_loc1[b][h][t] = bucket * NC + chunk;
    g_loc2[b][h][t] = bucket * NC + ((chunk + 1) & (NC - 1));
}

// Tensor-core attention. grid (NC, B), block 512 (16 warps), 2 blocks/SM.
// warp = (sg = s-tile of 16, zg = z/d-group of 32). QK: S = Q·K^T. PV: O = P·V.
__global__ void __launch_bounds__(512, 2)
k_attn(const float* __restrict__ qk, const float* __restrict__ v) {
    extern __shared__ char smemc[];
    int n = blockIdx.x, b = blockIdx.y;
    int tid = threadIdx.x, warp = tid >> 5, lane = tid & 31;
    int sg = warp >> 2, zg = warp & 3;
    int gid = lane >> 2, tig = lane & 3;

    int* qt  = (int*)(smemc + IOFF);
    int* qb  = qt + 64;
    int* kt  = qt + 128;
    int* kb  = qt + 256;
    int* ql1 = qt + 384;
    int* kl  = qt + 896;   // 128 x 16 ints: pairs {loc1[m], loc2[m]}
    float* rmax = (float*)(smemc + RMAXOFF);
    float* rsum = (float*)(smemc + RSUMOFF);

    int prev = (n + NC - 1) & (NC - 1);

    // ---- batched index loads (full MLP) ----
    int tfk[8], tfq[4];
#pragma unroll
    for (int u = 0; u < 8; u++) {
        int z = warp + 16 * u;
        int p = (z < 64) ? (n * BS + z) : (prev * BS + (z - 64));
        tfk[u] = g_sticker[b][p];
    }
#pragma unroll
    for (int u = 0; u < 4; u++) tfq[u] = g_sticker[b][n * BS + warp + 16 * u];

    // ---- gather K (normalized fp16) + V (fp16) + side data ----
#pragma unroll
    for (int u = 0; u < 8; u++) {
        int z = warp + 16 * u;
        int t = tfk[u] & (SL - 1), h = tfk[u] >> 12;
        float4 x = ((const float4*)(qk + ((size_t)b * SL + t) * D))[lane];
        float4 vx = ((const float4*)(v + ((size_t)b * SL + t) * D))[lane];
        float ss = x.x * x.x + x.y * x.y + x.z * x.z + x.w * x.w;
#pragma unroll
        for (int o = 16; o > 0; o >>= 1) ss += __shfl_xor_sync(0xffffffffu, ss, o);
        float inv = rsqrtf(fmaxf(ss, 1e-24f));
        __half2 k0 = __floats2half2_rn(x.x * inv, x.y * inv);
        __half2 k1 = __floats2half2_rn(x.z * inv, x.w * inv);
        *(uint2*)(smemc + KHOFF + z * RSB + 8 * lane) =
            make_uint2(*(uint32_t*)&k0, *(uint32_t*)&k1);
        __half2 v0 = __floats2half2_rn(vx.x, vx.y);
        __half2 v1 = __floats2half2_rn(vx.z, vx.w);
        *(uint2*)(smemc + VHOFF + z * RSB + 8 * lane) =
            make_uint2(*(uint32_t*)&v0, *(uint32_t*)&v1);
        if (lane == 0) { kt[z] = t; kb[z] = g_buckets[b][h][t]; }
        if (lane < 8)       kl[z * 16 + 2 * lane]           = g_loc1[b][lane][t];
        else if (lane < 16) kl[z * 16 + 2 * (lane - 8) + 1] = g_loc2[b][lane - 8][t];
    }
    // ---- gather Q (fp16) ----
#pragma unroll
    for (int u = 0; u < 4; u++) {
        int s = warp + 16 * u;
        int t = tfq[u] & (SL - 1), h = tfq[u] >> 12;
        float4 x = ((const float4*)(qk + ((size_t)b * SL + t) * D))[lane];
        __half2 q0 = __floats2half2_rn(x.x, x.y);
        __half2 q1 = __floats2half2_rn(x.z, x.w);
        *(uint2*)(smemc + QHOFF + s * RSB + 8 * lane) =
            make_uint2(*(uint32_t*)&q0, *(uint32_t*)&q1);
        if (lane == 0) { qt[s] = t; qb[s] = g_buckets[b][h][t]; }
        if (lane < 8) ql1[s * 8 + lane] = g_loc1[b][lane][t];
    }
    __syncthreads();

    // ---- QK via mma.sync: warp computes S[16 s, 32 z] over k=128 ----
    float acc[4][4];
#pragma unroll
    for (int nt = 0; nt < 4; nt++)
#pragma unroll
        for (int j = 0; j < 4; j++) acc[nt][j] = 0.f;

    uint32_t aQ = smem_u32(smemc) + QHOFF + (16 * sg + (lane & 15)) * RSB + ((lane >> 4) * 8) * 2;
    uint32_t aK = smem_u32(smemc) + KHOFF + (32 * zg + (lane & 7)) * RSB + (((lane >> 3) & 1) * 8) * 2;
#pragma unroll
    for (int k = 0; k < 8; k++) {
        uint32_t a0, a1, a2, a3;
        LDSM_X4(a0, a1, a2, a3, aQ + k * 32);
#pragma unroll
        for (int nt = 0; nt < 4; nt++) {
            uint32_t b0, b1;
            LDSM_X2(b0, b1, aK + nt * 8 * RSB + k * 32);
            MMA16816(acc[nt], a0, a1, a2, a3, b0, b1);
        }
    }

    // ---- masks + dup correction (C-frag mapping: rows gid/gid+8, cols 2tig/2tig+1) ----
    int s_a = 16 * sg + gid, s_b = s_a + 8;
    int qt_a = qt[s_a], qb_a = qb[s_a], qt_b = qt[s_b], qb_b = qb[s_b];
    int4 qa1 = *(int4*)&ql1[s_a * 8], qa2 = *(int4*)&ql1[s_a * 8 + 4];
    int4 qb1 = *(int4*)&ql1[s_b * 8], qb2 = *(int4*)&ql1[s_b * 8 + 4];
    const float scale = 0.08838834764831845f;
#pragma unroll
    for (int nt = 0; nt < 4; nt++) {
#pragma unroll
        for (int col = 0; col < 2; col++) {
            int z = 32 * zg + 8 * nt + 2 * tig + col;
            int ktv = kt[z], kbv = kb[z];
            int4 ka = *(int4*)&kl[z * 16 + 0];
            int4 kb4 = *(int4*)&kl[z * 16 + 4];
            int4 kc = *(int4*)&kl[z * 16 + 8];
            int4 kd = *(int4*)&kl[z * 16 + 12];
            // row s_a (c index col), row s_b (c index col+2)
            float va = acc[nt][col] * scale;
            float vb = acc[nt][col + 2] * scale;
            if (qt_a < ktv)  va = MNEG;
            if (qt_a == ktv) va = -10000.f;
            if (qb_a != kbv) va = MNEG;
            if (qt_b < ktv)  vb = MNEG;
            if (qt_b == ktv) vb = -10000.f;
            if (qb_b != kbv) vb = MNEG;
            int ca = 0, cb = 0;
            ca += (qa1.x == ka.x)  + (qa1.x == ka.y);
            ca += (qa1.y == ka.z)  + (qa1.y == ka.w);
            ca += (qa1.z == kb4.x) + (qa1.z == kb4.y);
            ca += (qa1.w == kb4.z) + (qa1.w == kb4.w);
            ca += (qa2.x == kc.x)  + (qa2.x == kc.y);
            ca += (qa2.y == kc.z)  + (qa2.y == kc.w);
            ca += (qa2.z == kd.x)  + (qa2.z == kd.y);
            ca += (qa2.w == kd.z)  + (qa2.w == kd.w);
            cb += (qb1.x == ka.x)  + (qb1.x == ka.y);
            cb += (qb1.y == ka.z)  + (qb1.y == ka.w);
            cb += (qb1.z == kb4.x) + (qb1.z == kb4.y);
            cb += (qb1.w == kb4.z) + (qb1.w == kb4.w);
            cb += (qb2.x == kc.x)  + (qb2.x == kc.y);
            cb += (qb2.y == kc.z)  + (qb2.y == kc.w);
            cb += (qb2.z == kd.x)  + (qb2.z == kd.y);
            cb += (qb2.w == kd.z)  + (qb2.w == kd.w);
            acc[nt][col]     = va - __logf((float)ca + 1e-9f);
            acc[nt][col + 2] = vb - __logf((float)cb + 1e-9f);
        }
    }

    // ---- softmax over z: quad-reduce + 4-warp (zg) combine via smem ----
    float mxa = MNEG, mxb = MNEG;
#pragma unroll
    for (int nt = 0; nt < 4; nt++) {
        mxa = fmaxf(mxa, fmaxf(acc[nt][0], acc[nt][1]));
        mxb = fmaxf(mxb, fmaxf(acc[nt][2], acc[nt][3]));
    }
#pragma unroll
    for (int o = 1; o <= 2; o <<= 1) {
        mxa = fmaxf(mxa, __shfl_xor_sync(0xffffffffu, mxa, o));
        mxb = fmaxf(mxb, __shfl_xor_sync(0xffffffffu, mxb, o));
    }
    if (tig == 0) { rmax[s_a * 4 + zg] = mxa; rmax[s_b * 4 + zg] = mxb; }
    __syncthreads();
    float4 ra = *(float4*)&rmax[s_a * 4];
    float4 rb = *(float4*)&rmax[s_b * 4];
    float ma = fmaxf(fmaxf(ra.x, ra.y), fmaxf(ra.z, ra.w));
    float mb = fmaxf(fmaxf(rb.x, rb.y), fmaxf(rb.z, rb.w));
    float sa = 0.f, sb = 0.f;
#pragma unroll
    for (int nt = 0; nt < 4; nt++) {
        acc[nt][0] = __expf(acc[nt][0] - ma);
        acc[nt][1] = __expf(acc[nt][1] - ma);
        acc[nt][2] = __expf(acc[nt][2] - mb);
        acc[nt][3] = __expf(acc[nt][3] - mb);
        sa += acc[nt][0] + acc[nt][1];
        sb += acc[nt][2] + acc[nt][3];
    }
#pragma unroll
    for (int o = 1; o <= 2; o <<= 1) {
        sa += __shfl_xor_sync(0xffffffffu, sa, o);
        sb += __shfl_xor_sync(0xffffffffu, sb, o);
    }
    if (tig == 0) { rsum[s_a * 4 + zg] = sa; rsum[s_b * 4 + zg] = sb; }
    __syncthreads();
    float4 sra = *(float4*)&rsum[s_a * 4];
    float4 srb = *(float4*)&rsum[s_b * 4];
    float suma = (sra.x + sra.y) + (sra.z + sra.w);
    float sumb = (srb.x + srb.y) + (srb.z + srb.w);
    float ia = 1.f / suma, ib = 1.f / sumb;
    // write P fp16 over the Q buffer (QK done; sync above covers all warps)
#pragma unroll
    for (int nt = 0; nt < 4; nt++) {
        int z0 = 32 * zg + 8 * nt + 2 * tig;
        __half2 pa = __floats2half2_rn(acc[nt][0] * ia, acc[nt][1] * ia);
        __half2 pb = __floats2half2_rn(acc[nt][2] * ib, acc[nt][3] * ib);
        *(__half2*)(smemc + QHOFF + s_a * RSB + z0 * 2) = pa;
        *(__half2*)(smemc + QHOFF + s_b * RSB + z0 * 2) = pb;
    }
    if (zg == 0 && tig == 0) {
        g_slog[b][n * BS + s_a] = ma + __logf(suma);
        g_slog[b][n * BS + s_b] = mb + __logf(sumb);
    }
    __syncthreads();

    // ---- PV via mma.sync: O[16 s, 32 d] = P[16 s,128 z] · V[128 z,32 d] ----
    float o[4][4];
#pragma unroll
    for (int nt = 0; nt < 4; nt++)
#pragma unroll
        for (int j = 0; j < 4; j++) o[nt][j] = 0.f;

    uint32_t aP = smem_u32(smemc) + QHOFF + (16 * sg + (lane & 15)) * RSB + ((lane >> 4) * 8) * 2;
    uint32_t aV = smem_u32(smemc) + VHOFF + (lane & 15) * RSB + (32 * zg) * 2;
#pragma unroll
    for (int k = 0; k < 8; k++) {
        uint32_t a0, a1, a2, a3;
        LDSM_X4(a0, a1, a2, a3, aP + k * 32);
#pragma unroll
        for (int nt = 0; nt < 4; nt++) {
            uint32_t b0, b1;
            LDSM_X2T(b0, b1, aV + k * 16 * RSB + nt * 16);
            MMA16816(o[nt], a0, a1, a2, a3, b0, b1);
        }
    }
#pragma unroll
    for (int nt = 0; nt < 4; nt++) {
        int d0 = 32 * zg + 8 * nt + 2 * tig;
        *(float2*)&g_so[b][n * BS + s_a][d0] = make_float2(o[nt][0], o[nt][1]);
        *(float2*)&g_so[b][n * BS + s_b][d0] = make_float2(o[nt][2], o[nt][3]);
    }
}

__global__ void k_combine(float* __restrict__ out) {
    int t = blockIdx.x, b = blockIdx.y;
    int d = threadIdx.x;
    int p[NH];
    float l[NH];
    float m = MNEG;
#pragma unroll
    for (int h = 0; h < NH; h++) {
        p[h] = g_undo[b][h * SL + t];
        l[h] = g_slog[b][p[h]];
        m = fmaxf(m, l[h]);
    }
    float sum = 0.f;
#pragma unroll
    for (int h = 0; h < NH; h++) { l[h] = __expf(l[h] - m); sum += l[h]; }
    float inv = 1.f / sum;
    float acc = 0.f;
#pragma unroll
    for (int h = 0; h < NH; h++) acc += l[h] * inv * g_so[b][p[h]][d];
    out[((size_t)b * SL + t) * D + d] = acc;
}

extern "C" void kernel_launch(void* const* d_in, const int* in_sizes, int n_in,
                              void* d_out, int out_size) {
    (void)in_sizes; (void)n_in; (void)out_size;
    const float* qk  = (const float*)d_in[0];
    const float* v   = (const float*)d_in[1];
    const float* rot = (const float*)d_in[2];
    float* out = (float*)d_out;

    cudaFuncSetAttribute(k_attn, cudaFuncAttributeMaxDynamicSharedMemorySize, SMEM_ATTN);

    k_zero_hist<<<B, NC>>>();
    k_buckets<<<dim3(SL / 256, NH, B), 256>>>(qk, rot);
    k_prefix<<<B, NC>>>();
    k_scatter<<<dim3(NC, B), 128>>>();
    k_loc<<<(B * NSL) / 256, 256>>>();
    k_attn<<<dim3(NC, B), 512, SMEM_ATTN>>>(qk, v);
    k_combine<<<dim3(SL, B), 128>>>(out);
}

// round 13
// speedup vs baseline: 1.6551x; 1.0636x over previous
#include <cuda_runtime.h>
#include <cuda_fp16.h>
#include <stdint.h>
#include <math.h>

#define B 8
#define SL 4096
#define D 128
#define NH 8
#define NB 64
#define NC 512
#define BS 64
#define NSL (NH*SL)
#define MNEG (-3.402823466e38f)

typedef unsigned long long ull;

__device__ __forceinline__ void fma2(ull& d, ull a, ull b) {
    asm("fma.rn.f32x2 %0, %1, %2, %0;" : "+l"(d) : "l"(a), "l"(b));
}
__device__ __forceinline__ ull pack2(float lo, float hi) {
    ull r; asm("mov.b64 %0, {%1, %2};" : "=l"(r) : "f"(lo), "f"(hi)); return r;
}
__device__ __forceinline__ float2 unpack2(ull v) {
    float2 r; asm("mov.b64 {%0, %1}, %2;" : "=f"(r.x), "=f"(r.y) : "l"(v)); return r;
}
__device__ __forceinline__ uint32_t smem_u32(const void* p) {
    uint32_t a;
    asm("{ .reg .u64 t; cvta.to.shared.u64 t, %1; cvt.u32.u64 %0, t; }" : "=r"(a) : "l"(p));
    return a;
}

// ---- warp-level tensor core primitives (portable PTX, HMMA pipe) ----
#define LDSM_X4(r0, r1, r2, r3, a) \
    asm volatile("ldmatrix.sync.aligned.m8n8.x4.shared.b16 {%0,%1,%2,%3}, [%4];" \
        : "=r"(r0), "=r"(r1), "=r"(r2), "=r"(r3) : "r"(a))
#define LDSM_X2(r0, r1, a) \
    asm volatile("ldmatrix.sync.aligned.m8n8.x2.shared.b16 {%0,%1}, [%2];" \
        : "=r"(r0), "=r"(r1) : "r"(a))
#define LDSM_X2T(r0, r1, a) \
    asm volatile("ldmatrix.sync.aligned.m8n8.x2.trans.shared.b16 {%0,%1}, [%2];" \
        : "=r"(r0), "=r"(r1) : "r"(a))
#define MMA16816(c, a0, a1, a2, a3, b0, b1) \
    asm volatile("mma.sync.aligned.m16n8k16.row.col.f32.f16.f16.f32 " \
        "{%0,%1,%2,%3}, {%4,%5,%6,%7}, {%8,%9}, {%0,%1,%2,%3};" \
        : "+f"((c)[0]), "+f"((c)[1]), "+f"((c)[2]), "+f"((c)[3]) \
        : "r"(a0), "r"(a1), "r"(a2), "r"(a3), "r"(b0), "r"(b1))

// ---- k_attn smem layout (bytes). fp16 rows, stride 136 halves = 272 B ----
#define RSB 272
#define QHOFF 0         // Q fp16 64 rows; reused as P fp16
#define KHOFF 17408     // K fp16 128 rows (normalized)
#define VHOFF 52224     // V fp16 128 rows
#define IOFF  87040     // ints: qt64 qb64 kt128 kb128 ql1[512] kl[2048]
#define RMAXOFF 98816   // float[64*4]
#define RSUMOFF 99840   // float[64*4]
#define SMEM_ATTN 100864

// ---------------- scratch ----------------------------------------------------
__device__ int    g_buckets[B][NH][SL];
__device__ int    g_hist[B][NC];
__device__ int    g_boff[B][NC];
__device__ int    g_sticker[B][NSL];
__device__ int    g_undo[B][NSL];
__device__ int    g_loc1[B][NH][SL];
__device__ int    g_loc2[B][NH][SL];
__device__ __half g_so[B][NSL][D];     // fp16 sorted attention output (67 MB)
__device__ float  g_slog[B][NSL];

__global__ void k_zero_hist() { g_hist[blockIdx.x][threadIdx.x] = 0; }

__global__ void k_buckets(const float* __restrict__ qk, const float* __restrict__ rot) {
    __shared__ float rs[32 * 32];
    __shared__ float qt_[256 * 33];
    int b = blockIdx.z, h = blockIdx.y, tid = threadIdx.x;
    int s0 = blockIdx.x * 256;
    ull acc2[16];
#pragma unroll
    for (int n = 0; n < 16; n++) acc2[n] = 0ull;
    for (int d0 = 0; d0 < 128; d0 += 32) {
        for (int i = tid; i < 32 * 32; i += 256) {
            int dd = i >> 5, nn = i & 31;
            rs[i] = rot[((size_t)(d0 + dd) * NH + h) * 32 + nn];
        }
        for (int i = tid; i < 256 * 32; i += 256) {
            int r = i >> 5, c = i & 31;
            qt_[r * 33 + c] = qk[((size_t)b * SL + s0 + r) * D + d0 + c];
        }
        __syncthreads();
#pragma unroll 4
        for (int dd = 0; dd < 32; dd++) {
            float qv = qt_[tid * 33 + dd];
            ull qq = pack2(qv, qv);
            const ull* r2 = (const ull*)&rs[dd * 32];
#pragma unroll
            for (int n = 0; n < 16; n++) fma2(acc2[n], qq, r2[n]);
        }
        __syncthreads();
    }
    float acc[32];
#pragma unroll
    for (int n = 0; n < 16; n++) { float2 p = unpack2(acc2[n]); acc[2*n] = p.x; acc[2*n+1] = p.y; }
    float best = acc[0]; int idx = 0;
#pragma unroll
    for (int n = 1; n < 32; n++) if (acc[n] > best) { best = acc[n]; idx = n; }
#pragma unroll
    for (int n = 0; n < 32; n++) if (-acc[n] > best) { best = -acc[n]; idx = 32 + n; }
    int bucket = idx + h * NB;
    g_buckets[b][h][s0 + tid] = bucket;
    atomicAdd(&g_hist[b][bucket], 1);
}

__global__ void k_prefix() {
    __shared__ int sh[NC];
    int b = blockIdx.x, tid = threadIdx.x;
    int v = g_hist[b][tid];
    sh[tid] = v;
    __syncthreads();
#pragma unroll
    for (int off = 1; off < NC; off <<= 1) {
        int x = (tid >= off) ? sh[tid - off] : 0;
        __syncthreads();
        sh[tid] += x;
        __syncthreads();
    }
    g_boff[b][tid] = sh[tid] - v;
}

__global__ void k_scatter() {
    int bk = blockIdx.x, b = blockIdx.y;
    int h = bk >> 6;
    int warp = threadIdx.x >> 5, lane = threadIdx.x & 31;
    const int* bb = &g_buckets[b][h][0];
    int t0 = warp * (SL / 4);
    __shared__ int wc[4];
    int cnt = 0;
    for (int base = 0; base < SL / 4; base += 32) {
        bool m = (bb[t0 + base + lane] == bk);
        cnt += __popc(__ballot_sync(0xffffffffu, m));
    }
    if (lane == 0) wc[warp] = cnt;
    __syncthreads();
    int pos = g_boff[b][bk];
#pragma unroll
    for (int w = 0; w < 4; w++) if (w < warp) pos += wc[w];
    for (int base = 0; base < SL / 4; base += 32) {
        int t = t0 + base + lane;
        bool m = (bb[t] == bk);
        unsigned bal = __ballot_sync(0xffffffffu, m);
        if (m) {
            int r = __popc(bal & ((1u << lane) - 1));
            int j = h * SL + t;
            g_sticker[b][pos + r] = j;
            g_undo[b][j] = pos + r;
        }
        pos += __popc(bal);
    }
}

__global__ void k_loc() {
    int idx = blockIdx.x * 256 + threadIdx.x;
    int b = idx / NSL, r = idx % NSL;
    int h = r >> 12, t = r & (SL - 1);
    int chunk = g_undo[b][r] >> 6;
    int bucket = g_buckets[b][h][t];
    g_loc1[b][h][t] = bucket * NC + chunk;
    g_loc2[b][h][t] = bucket * NC + ((chunk + 1) & (NC - 1));
}

// Tensor-core attention. grid (NC, B), block 512 (16 warps), 2 blocks/SM.
__global__ void __launch_bounds__(512, 2)
k_attn(const float* __restrict__ qk, const float* __restrict__ v) {
    extern __shared__ char smemc[];
    int n = blockIdx.x, b = blockIdx.y;
    int tid = threadIdx.x, warp = tid >> 5, lane = tid & 31;
    int sg = warp >> 2, zg = warp & 3;
    int gid = lane >> 2, tig = lane & 3;

    int* qt  = (int*)(smemc + IOFF);
    int* qb  = qt + 64;
    int* kt  = qt + 128;
    int* kb  = qt + 256;
    int* ql1 = qt + 384;
    int* kl  = qt + 896;
    float* rmax = (float*)(smemc + RMAXOFF);
    float* rsum = (float*)(smemc + RSUMOFF);

    int prev = (n + NC - 1) & (NC - 1);

    // ---- batched index loads (full MLP) ----
    int tfq[4], tfp[4], tfv[8];
#pragma unroll
    for (int u = 0; u < 4; u++) {
        tfq[u] = g_sticker[b][n * BS + warp + 16 * u];          // current rows (Q & K z<64)
        tfp[u] = g_sticker[b][prev * BS + warp + 16 * u];       // prev rows (K z>=64)
    }
#pragma unroll
    for (int u = 0; u < 8; u++) {
        int z = warp + 16 * u;
        int p = (z < 64) ? (n * BS + z) : (prev * BS + (z - 64));
        tfv[u] = g_sticker[b][p];
    }

    // ---- current rows: one fp32 load -> Q fp16 (raw) + K fp16 (normalized) ----
#pragma unroll
    for (int u = 0; u < 4; u++) {
        int s = warp + 16 * u;                  // also z = s for K
        int t = tfq[u] & (SL - 1), h = tfq[u] >> 12;
        float4 x = ((const float4*)(qk + ((size_t)b * SL + t) * D))[lane];
        __half2 q0 = __floats2half2_rn(x.x, x.y);
        __half2 q1 = __floats2half2_rn(x.z, x.w);
        *(uint2*)(smemc + QHOFF + s * RSB + 8 * lane) =
            make_uint2(*(uint32_t*)&q0, *(uint32_t*)&q1);
        float ss = x.x * x.x + x.y * x.y + x.z * x.z + x.w * x.w;
#pragma unroll
        for (int o = 16; o > 0; o >>= 1) ss += __shfl_xor_sync(0xffffffffu, ss, o);
        float inv = rsqrtf(fmaxf(ss, 1e-24f));
        __half2 k0 = __floats2half2_rn(x.x * inv, x.y * inv);
        __half2 k1 = __floats2half2_rn(x.z * inv, x.w * inv);
        *(uint2*)(smemc + KHOFF + s * RSB + 8 * lane) =
            make_uint2(*(uint32_t*)&k0, *(uint32_t*)&k1);
        if (lane == 0) { qt[s] = t; qb[s] = g_buckets[b][h][t]; kt[s] = t; kb[s] = qb[s]; }
        if (lane < 8) {
            int l1 = g_loc1[b][lane][t];
            ql1[s * 8 + lane] = l1;
            kl[s * 16 + 2 * lane] = l1;
        } else if (lane < 16) kl[s * 16 + 2 * (lane - 8) + 1] = g_loc2[b][lane - 8][t];
    }
    // ---- prev rows: K fp16 normalized only (z = 64 + s) ----
#pragma unroll
    for (int u = 0; u < 4; u++) {
        int z = 64 + warp + 16 * u;
        int t = tfp[u] & (SL - 1), h = tfp[u] >> 12;
        float4 x = ((const float4*)(qk + ((size_t)b * SL + t) * D))[lane];
        float ss = x.x * x.x + x.y * x.y + x.z * x.z + x.w * x.w;
#pragma unroll
        for (int o = 16; o > 0; o >>= 1) ss += __shfl_xor_sync(0xffffffffu, ss, o);
        float inv = rsqrtf(fmaxf(ss, 1e-24f));
        __half2 k0 = __floats2half2_rn(x.x * inv, x.y * inv);
        __half2 k1 = __floats2half2_rn(x.z * inv, x.w * inv);
        *(uint2*)(smemc + KHOFF + z * RSB + 8 * lane) =
            make_uint2(*(uint32_t*)&k0, *(uint32_t*)&k1);
        if (lane == 0) { kt[z] = t; kb[z] = g_buckets[b][h][t]; }
        if (lane < 8)       kl[z * 16 + 2 * lane]           = g_loc1[b][lane][t];
        else if (lane < 16) kl[z * 16 + 2 * (lane - 8) + 1] = g_loc2[b][lane - 8][t];
    }
    // ---- V rows fp16 ----
#pragma unroll
    for (int u = 0; u < 8; u++) {
        int z = warp + 16 * u;
        int t = tfv[u] & (SL - 1);
        float4 vx = ((const float4*)(v + ((size_t)b * SL + t) * D))[lane];
        __half2 v0 = __floats2half2_rn(vx.x, vx.y);
        __half2 v1 = __floats2half2_rn(vx.z, vx.w);
        *(uint2*)(smemc + VHOFF + z * RSB + 8 * lane) =
            make_uint2(*(uint32_t*)&v0, *(uint32_t*)&v1);
    }
    __syncthreads();

    // ---- QK via mma.sync: warp computes S[16 s, 32 z] over k=128 ----
    float acc[4][4];
#pragma unroll
    for (int nt = 0; nt < 4; nt++)
#pragma unroll
        for (int j = 0; j < 4; j++) acc[nt][j] = 0.f;

    uint32_t aQ = smem_u32(smemc) + QHOFF + (16 * sg + (lane & 15)) * RSB + ((lane >> 4) * 8) * 2;
    uint32_t aK = smem_u32(smemc) + KHOFF + (32 * zg + (lane & 7)) * RSB + (((lane >> 3) & 1) * 8) * 2;
#pragma unroll
    for (int k = 0; k < 8; k++) {
        uint32_t a0, a1, a2, a3;
        LDSM_X4(a0, a1, a2, a3, aQ + k * 32);
#pragma unroll
        for (int nt = 0; nt < 4; nt++) {
            uint32_t b0, b1;
            LDSM_X2(b0, b1, aK + nt * 8 * RSB + k * 32);
            MMA16816(acc[nt], a0, a1, a2, a3, b0, b1);
        }
    }

    // ---- masks + dup correction ----
    int s_a = 16 * sg + gid, s_b = s_a + 8;
    int qt_a = qt[s_a], qb_a = qb[s_a], qt_b = qt[s_b], qb_b = qb[s_b];
    int4 qa1 = *(int4*)&ql1[s_a * 8], qa2 = *(int4*)&ql1[s_a * 8 + 4];
    int4 qb1 = *(int4*)&ql1[s_b * 8], qb2 = *(int4*)&ql1[s_b * 8 + 4];
    const float scale = 0.08838834764831845f;
#pragma unroll
    for (int nt = 0; nt < 4; nt++) {
#pragma unroll
        for (int col = 0; col < 2; col++) {
            int z = 32 * zg + 8 * nt + 2 * tig + col;
            int ktv = kt[z], kbv = kb[z];
            int4 ka = *(int4*)&kl[z * 16 + 0];
            int4 kb4 = *(int4*)&kl[z * 16 + 4];
            int4 kc = *(int4*)&kl[z * 16 + 8];
            int4 kd = *(int4*)&kl[z * 16 + 12];
            float va = acc[nt][col] * scale;
            float vb = acc[nt][col + 2] * scale;
            if (qt_a < ktv)  va = MNEG;
            if (qt_a == ktv) va = -10000.f;
            if (qb_a != kbv) va = MNEG;
            if (qt_b < ktv)  vb = MNEG;
            if (qt_b == ktv) vb = -10000.f;
            if (qb_b != kbv) vb = MNEG;
            int ca = 0, cb = 0;
            ca += (qa1.x == ka.x)  + (qa1.x == ka.y);
            ca += (qa1.y == ka.z)  + (qa1.y == ka.w);
            ca += (qa1.z == kb4.x) + (qa1.z == kb4.y);
            ca += (qa1.w == kb4.z) + (qa1.w == kb4.w);
            ca += (qa2.x == kc.x)  + (qa2.x == kc.y);
            ca += (qa2.y == kc.z)  + (qa2.y == kc.w);
            ca += (qa2.z == kd.x)  + (qa2.z == kd.y);
            ca += (qa2.w == kd.z)  + (qa2.w == kd.w);
            cb += (qb1.x == ka.x)  + (qb1.x == ka.y);
            cb += (qb1.y == ka.z)  + (qb1.y == ka.w);
            cb += (qb1.z == kb4.x) + (qb1.z == kb4.y);
            cb += (qb1.w == kb4.z) + (qb1.w == kb4.w);
            cb += (qb2.x == kc.x)  + (qb2.x == kc.y);
            cb += (qb2.y == kc.z)  + (qb2.y == kc.w);
            cb += (qb2.z == kd.x)  + (qb2.z == kd.y);
            cb += (qb2.w == kd.z)  + (qb2.w == kd.w);
            acc[nt][col]     = va - __logf((float)ca + 1e-9f);
            acc[nt][col + 2] = vb - __logf((float)cb + 1e-9f);
        }
    }

    // ---- single-pass local softmax (max + sum at local max), one combine sync ----
    float mxa = MNEG, mxb = MNEG;
#pragma unroll
    for (int nt = 0; nt < 4; nt++) {
        mxa = fmaxf(mxa, fmaxf(acc[nt][0], acc[nt][1]));
        mxb = fmaxf(mxb, fmaxf(acc[nt][2], acc[nt][3]));
    }
#pragma unroll
    for (int o = 1; o <= 2; o <<= 1) {
        mxa = fmaxf(mxa, __shfl_xor_sync(0xffffffffu, mxa, o));
        mxb = fmaxf(mxb, __shfl_xor_sync(0xffffffffu, mxb, o));
    }
    float sa = 0.f, sb = 0.f;
#pragma unroll
    for (int nt = 0; nt < 4; nt++) {
        acc[nt][0] = __expf(acc[nt][0] - mxa);
        acc[nt][1] = __expf(acc[nt][1] - mxa);
        acc[nt][2] = __expf(acc[nt][2] - mxb);
        acc[nt][3] = __expf(acc[nt][3] - mxb);
        sa += acc[nt][0] + acc[nt][1];
        sb += acc[nt][2] + acc[nt][3];
    }
#pragma unroll
    for (int o = 1; o <= 2; o <<= 1) {
        sa += __shfl_xor_sync(0xffffffffu, sa, o);
        sb += __shfl_xor_sync(0xffffffffu, sb, o);
    }
    if (tig == 0) {
        rmax[s_a * 4 + zg] = mxa; rmax[s_b * 4 + zg] = mxb;
        rsum[s_a * 4 + zg] = sa;  rsum[s_b * 4 + zg] = sb;
    }
    __syncthreads();   // also guarantees all QK ldmatrix reads done (P overwrites Q next)

    float4 ra = *(float4*)&rmax[s_a * 4];
    float4 rb = *(float4*)&rmax[s_b * 4];
    float ma = fmaxf(fmaxf(ra.x, ra.y), fmaxf(ra.z, ra.w));
    float mb = fmaxf(fmaxf(rb.x, rb.y), fmaxf(rb.z, rb.w));
    float4 sra = *(float4*)&rsum[s_a * 4];
    float4 srb = *(float4*)&rsum[s_b * 4];
    float suma = sra.x * __expf(ra.x - ma) + sra.y * __expf(ra.y - ma)
               + sra.z * __expf(ra.z - ma) + sra.w * __expf(ra.w - ma);
    float sumb = srb.x * __expf(rb.x - mb) + srb.y * __expf(rb.y - mb)
               + srb.z * __expf(rb.z - mb) + srb.w * __expf(rb.w - mb);
    float fa = __expf(mxa - ma) / suma;   // local-exp -> global prob factor
    float fb = __expf(mxb - mb) / sumb;
#pragma unroll
    for (int nt = 0; nt < 4; nt++) {
        int z0 = 32 * zg + 8 * nt + 2 * tig;
        __half2 pa = __floats2half2_rn(acc[nt][0] * fa, acc[nt][1] * fa);
        __half2 pb = __floats2half2_rn(acc[nt][2] * fb, acc[nt][3] * fb);
        *(__half2*)(smemc + QHOFF + s_a * RSB + z0 * 2) = pa;
        *(__half2*)(smemc + QHOFF + s_b * RSB + z0 * 2) = pb;
    }
    if (zg == 0 && tig == 0) {
        g_slog[b][n * BS + s_a] = ma + __logf(suma);
        g_slog[b][n * BS + s_b] = mb + __logf(sumb);
    }
    __syncthreads();

    // ---- PV via mma.sync: O[16 s, 32 d] = P · V ----
    float o[4][4];
#pragma unroll
    for (int nt = 0; nt < 4; nt++)
#pragma unroll
        for (int j = 0; j < 4; j++) o[nt][j] = 0.f;

    uint32_t aP = smem_u32(smemc) + QHOFF + (16 * sg + (lane & 15)) * RSB + ((lane >> 4) * 8) * 2;
    uint32_t aV = smem_u32(smemc) + VHOFF + (lane & 15) * RSB + (32 * zg) * 2;
#pragma unroll
    for (int k = 0; k < 8; k++) {
        uint32_t a0, a1, a2, a3;
        LDSM_X4(a0, a1, a2, a3, aP + k * 32);
#pragma unroll
        for (int nt = 0; nt < 4; nt++) {
            uint32_t b0, b1;
            LDSM_X2T(b0, b1, aV + k * 16 * RSB + nt * 16);
            MMA16816(o[nt], a0, a1, a2, a3, b0, b1);
        }
    }
#pragma unroll
    for (int nt = 0; nt < 4; nt++) {
        int d0 = 32 * zg + 8 * nt + 2 * tig;
        *(__half2*)&g_so[b][n * BS + s_a][d0] = __floats2half2_rn(o[nt][0], o[nt][1]);
        *(__half2*)&g_so[b][n * BS + s_b][d0] = __floats2half2_rn(o[nt][2], o[nt][3]);
    }
}

__global__ void k_combine(float* __restrict__ out) {
    int t = blockIdx.x, b = blockIdx.y;
    int d = threadIdx.x;
    int p[NH];
    float l[NH];
    float m = MNEG;
#pragma unroll
    for (int h = 0; h < NH; h++) {
        p[h] = g_undo[b][h * SL + t];
        l[h] = g_slog[b][p[h]];
        m = fmaxf(m, l[h]);
    }
    float sum = 0.f;
#pragma unroll
    for (int h = 0; h < NH; h++) { l[h] = __expf(l[h] - m); sum += l[h]; }
    float inv = 1.f / sum;
    float acc = 0.f;
#pragma unroll
    for (int h = 0; h < NH; h++) acc += l[h] * inv * __half2float(g_so[b][p[h]][d]);
    out[((size_t)b * SL + t) * D + d] = acc;
}

extern "C" void kernel_launch(void* const* d_in, const int* in_sizes, int n_in,
                              void* d_out, int out_size) {
    (void)in_sizes; (void)n_in; (void)out_size;
    const float* qk  = (const float*)d_in[0];
    const float* v   = (const float*)d_in[1];
    const float* rot = (const float*)d_in[2];
    float* out = (float*)d_out;

    cudaFuncSetAttribute(k_attn, cudaFuncAttributeMaxDynamicSharedMemorySize, SMEM_ATTN);

    k_zero_hist<<<B, NC>>>();
    k_buckets<<<dim3(SL / 256, NH, B), 256>>>(qk, rot);
    k_prefix<<<B, NC>>>();
    k_scatter<<<dim3(NC, B), 128>>>();
    k_loc<<<(B * NSL) / 256, 256>>>();
    k_attn<<<dim3(NC, B), 512, SMEM_ATTN>>>(qk, v);
    k_combine<<<dim3(SL, B), 128>>>(out);
}

// round 14
// speedup vs baseline: 1.7813x; 1.0763x over previous
#include <cuda_runtime.h>
#include <cuda_fp16.h>
#include <stdint.h>
#include <math.h>

#define B 8
#define SL 4096
#define D 128
#define NH 8
#define NB 64
#define NC 512
#define BS 64
#define NSL (NH*SL)
#define MNEG (-3.402823466e38f)

typedef unsigned long long ull;

__device__ __forceinline__ void fma2(ull& d, ull a, ull b) {
    asm("fma.rn.f32x2 %0, %1, %2, %0;" : "+l"(d) : "l"(a), "l"(b));
}
__device__ __forceinline__ ull pack2(float lo, float hi) {
    ull r; asm("mov.b64 %0, {%1, %2};" : "=l"(r) : "f"(lo), "f"(hi)); return r;
}
__device__ __forceinline__ float2 unpack2(ull v) {
    float2 r; asm("mov.b64 {%0, %1}, %2;" : "=f"(r.x), "=f"(r.y) : "l"(v)); return r;
}
__device__ __forceinline__ uint32_t smem_u32(const void* p) {
    uint32_t a;
    asm("{ .reg .u64 t; cvta.to.shared.u64 t, %1; cvt.u32.u64 %0, t; }" : "=r"(a) : "l"(p));
    return a;
}

// ---- warp-level tensor core primitives (portable PTX, HMMA pipe) ----
#define LDSM_X4(r0, r1, r2, r3, a) \
    asm volatile("ldmatrix.sync.aligned.m8n8.x4.shared.b16 {%0,%1,%2,%3}, [%4];" \
        : "=r"(r0), "=r"(r1), "=r"(r2), "=r"(r3) : "r"(a))
#define LDSM_X2(r0, r1, a) \
    asm volatile("ldmatrix.sync.aligned.m8n8.x2.shared.b16 {%0,%1}, [%2];" \
        : "=r"(r0), "=r"(r1) : "r"(a))
#define LDSM_X2T(r0, r1, a) \
    asm volatile("ldmatrix.sync.aligned.m8n8.x2.trans.shared.b16 {%0,%1}, [%2];" \
        : "=r"(r0), "=r"(r1) : "r"(a))
#define MMA16816(c, a0, a1, a2, a3, b0, b1) \
    asm volatile("mma.sync.aligned.m16n8k16.row.col.f32.f16.f16.f32 " \
        "{%0,%1,%2,%3}, {%4,%5,%6,%7}, {%8,%9}, {%0,%1,%2,%3};" \
        : "+f"((c)[0]), "+f"((c)[1]), "+f"((c)[2]), "+f"((c)[3]) \
        : "r"(a0), "r"(a1), "r"(a2), "r"(a3), "r"(b0), "r"(b1))

// ---- k_attn smem layout (bytes). fp16 rows, stride 136 halves = 272 B ----
#define RSB 272
#define QHOFF 0         // Q fp16 64 rows; reused as P fp16
#define KHOFF 17408     // K fp16 128 rows (normalized)
#define VHOFF 52224     // V fp16 128 rows
#define IOFF  87040     // ints: qt64 qb64 kt128 kb128 ql1[512] kl[2048]
#define RMAXOFF 98816   // float[64*4]
#define RSUMOFF 99840   // float[64*4]
#define SMEM_ATTN 100864

// ---------------- scratch ----------------------------------------------------
__device__ int    g_buckets[B][NH][SL];
__device__ int    g_hist[B][NC];
__device__ int    g_boff[B][NC];
__device__ int    g_sticker[B][NSL];
__device__ int    g_undo[B][NSL];
__device__ int    g_locT[B][SL][16];   // interleaved {loc1[h], loc2[h]} pairs
__device__ __half g_so[B][NSL][D];
__device__ float  g_slog[B][NSL];

__global__ void k_zero_hist() { g_hist[blockIdx.x][threadIdx.x] = 0; }

__global__ void k_buckets(const float* __restrict__ qk, const float* __restrict__ rot) {
    __shared__ float rs[32 * 32];
    __shared__ float qt_[256 * 33];
    int b = blockIdx.z, h = blockIdx.y, tid = threadIdx.x;
    int s0 = blockIdx.x * 256;
    ull acc2[16];
#pragma unroll
    for (int n = 0; n < 16; n++) acc2[n] = 0ull;
    for (int d0 = 0; d0 < 128; d0 += 32) {
        for (int i = tid; i < 32 * 32; i += 256) {
            int dd = i >> 5, nn = i & 31;
            rs[i] = rot[((size_t)(d0 + dd) * NH + h) * 32 + nn];
        }
        for (int i = tid; i < 256 * 32; i += 256) {
            int r = i >> 5, c = i & 31;
            qt_[r * 33 + c] = qk[((size_t)b * SL + s0 + r) * D + d0 + c];
        }
        __syncthreads();
#pragma unroll 4
        for (int dd = 0; dd < 32; dd++) {
            float qv = qt_[tid * 33 + dd];
            ull qq = pack2(qv, qv);
            const ull* r2 = (const ull*)&rs[dd * 32];
#pragma unroll
            for (int n = 0; n < 16; n++) fma2(acc2[n], qq, r2[n]);
        }
        __syncthreads();
    }
    float acc[32];
#pragma unroll
    for (int n = 0; n < 16; n++) { float2 p = unpack2(acc2[n]); acc[2*n] = p.x; acc[2*n+1] = p.y; }
    float best = acc[0]; int idx = 0;
#pragma unroll
    for (int n = 1; n < 32; n++) if (acc[n] > best) { best = acc[n]; idx = n; }
#pragma unroll
    for (int n = 0; n < 32; n++) if (-acc[n] > best) { best = -acc[n]; idx = 32 + n; }
    int bucket = idx + h * NB;
    g_buckets[b][h][s0 + tid] = bucket;
    atomicAdd(&g_hist[b][bucket], 1);
}

__global__ void k_prefix() {
    __shared__ int sh[NC];
    int b = blockIdx.x, tid = threadIdx.x;
    int v = g_hist[b][tid];
    sh[tid] = v;
    __syncthreads();
#pragma unroll
    for (int off = 1; off < NC; off <<= 1) {
        int x = (tid >= off) ? sh[tid - off] : 0;
        __syncthreads();
        sh[tid] += x;
        __syncthreads();
    }
    g_boff[b][tid] = sh[tid] - v;
}

__global__ void k_scatter() {
    int bk = blockIdx.x, b = blockIdx.y;
    int h = bk >> 6;
    int warp = threadIdx.x >> 5, lane = threadIdx.x & 31;
    const int* bb = &g_buckets[b][h][0];
    int t0 = warp * (SL / 4);
    __shared__ int wc[4];
    int cnt = 0;
    for (int base = 0; base < SL / 4; base += 32) {
        bool m = (bb[t0 + base + lane] == bk);
        cnt += __popc(__ballot_sync(0xffffffffu, m));
    }
    if (lane == 0) wc[warp] = cnt;
    __syncthreads();
    int pos = g_boff[b][bk];
#pragma unroll
    for (int w = 0; w < 4; w++) if (w < warp) pos += wc[w];
    for (int base = 0; base < SL / 4; base += 32) {
        int t = t0 + base + lane;
        bool m = (bb[t] == bk);
        unsigned bal = __ballot_sync(0xffffffffu, m);
        if (m) {
            int r = __popc(bal & ((1u << lane) - 1));
            int j = h * SL + t;
            g_sticker[b][pos + r] = j;
            g_undo[b][j] = pos + r;
        }
        pos += __popc(bal);
    }
}

// loc codes, transposed layout: thread per (b, t); one 64B coalesced store.
__global__ void k_loc() {
    int idx = blockIdx.x * 128 + threadIdx.x;
    int b = idx >> 12, t = idx & (SL - 1);
    int val[16];
#pragma unroll
    for (int h = 0; h < NH; h++) {
        int bucket = g_buckets[b][h][t];
        int chunk = g_undo[b][h * SL + t] >> 6;
        val[2 * h]     = bucket * NC + chunk;
        val[2 * h + 1] = bucket * NC + ((chunk + 1) & (NC - 1));
    }
    int4* dst = (int4*)&g_locT[b][t][0];
#pragma unroll
    for (int j = 0; j < 4; j++)
        dst[j] = make_int4(val[4 * j], val[4 * j + 1], val[4 * j + 2], val[4 * j + 3]);
}

// Tensor-core attention. grid (NC, B), block 512 (16 warps), 2 blocks/SM.
__global__ void __launch_bounds__(512, 2)
k_attn(const float* __restrict__ qk, const float* __restrict__ v) {
    extern __shared__ char smemc[];
    int n = blockIdx.x, b = blockIdx.y;
    int tid = threadIdx.x, warp = tid >> 5, lane = tid & 31;
    int sg = warp >> 2, zg = warp & 3;
    int gid = lane >> 2, tig = lane & 3;

    int* qt  = (int*)(smemc + IOFF);
    int* qb  = qt + 64;
    int* kt  = qt + 128;
    int* kb  = qt + 256;
    int* ql1 = qt + 384;
    int* kl  = qt + 896;
    float* rmax = (float*)(smemc + RMAXOFF);
    float* rsum = (float*)(smemc + RSUMOFF);

    int prev = (n + NC - 1) & (NC - 1);

    // ---- batched index loads (full MLP) ----
    int tfq[4], tfp[4], tfv[8];
#pragma unroll
    for (int u = 0; u < 4; u++) {
        tfq[u] = g_sticker[b][n * BS + warp + 16 * u];
        tfp[u] = g_sticker[b][prev * BS + warp + 16 * u];
    }
#pragma unroll
    for (int u = 0; u < 8; u++) {
        int z = warp + 16 * u;
        int p = (z < 64) ? (n * BS + z) : (prev * BS + (z - 64));
        tfv[u] = g_sticker[b][p];
    }

    // ---- current rows: one fp32 load -> Q fp16 (raw) + K fp16 (normalized) ----
#pragma unroll
    for (int u = 0; u < 4; u++) {
        int s = warp + 16 * u;
        int t = tfq[u] & (SL - 1), h = tfq[u] >> 12;
        float4 x = ((const float4*)(qk + ((size_t)b * SL + t) * D))[lane];
        __half2 q0 = __floats2half2_rn(x.x, x.y);
        __half2 q1 = __floats2half2_rn(x.z, x.w);
        *(uint2*)(smemc + QHOFF + s * RSB + 8 * lane) =
            make_uint2(*(uint32_t*)&q0, *(uint32_t*)&q1);
        float ss = x.x * x.x + x.y * x.y + x.z * x.z + x.w * x.w;
#pragma unroll
        for (int o = 16; o > 0; o >>= 1) ss += __shfl_xor_sync(0xffffffffu, ss, o);
        float inv = rsqrtf(fmaxf(ss, 1e-24f));
        __half2 k0 = __floats2half2_rn(x.x * inv, x.y * inv);
        __half2 k1 = __floats2half2_rn(x.z * inv, x.w * inv);
        *(uint2*)(smemc + KHOFF + s * RSB + 8 * lane) =
            make_uint2(*(uint32_t*)&k0, *(uint32_t*)&k1);
        if (lane == 0) { qt[s] = t; kt[s] = t; }
        if (lane < 4) {
            int4 lv = ((const int4*)&g_locT[b][t][0])[lane];
            *(int4*)&kl[s * 16 + 4 * lane] = lv;
            ql1[s * 8 + 2 * lane]     = lv.x;
            ql1[s * 8 + 2 * lane + 1] = lv.z;
            if (lane == (h >> 1)) {
                int bkt = ((h & 1) ? lv.z : lv.x) >> 9;   // loc1 = bucket*512 + chunk
                kb[s] = bkt; qb[s] = bkt;
            }
        }
    }
    // ---- prev rows: K fp16 normalized only (z = 64 + s) ----
#pragma unroll
    for (int u = 0; u < 4; u++) {
        int z = 64 + warp + 16 * u;
        int t = tfp[u] & (SL - 1), h = tfp[u] >> 12;
        float4 x = ((const float4*)(qk + ((size_t)b * SL + t) * D))[lane];
        float ss = x.x * x.x + x.y * x.y + x.z * x.z + x.w * x.w;
#pragma unroll
        for (int o = 16; o > 0; o >>= 1) ss += __shfl_xor_sync(0xffffffffu, ss, o);
        float inv = rsqrtf(fmaxf(ss, 1e-24f));
        __half2 k0 = __floats2half2_rn(x.x * inv, x.y * inv);
        __half2 k1 = __floats2half2_rn(x.z * inv, x.w * inv);
        *(uint2*)(smemc + KHOFF + z * RSB + 8 * lane) =
            make_uint2(*(uint32_t*)&k0, *(uint32_t*)&k1);
        if (lane == 0) kt[z] = t;
        if (lane < 4) {
            int4 lv = ((const int4*)&g_locT[b][t][0])[lane];
            *(int4*)&kl[z * 16 + 4 * lane] = lv;
            if (lane == (h >> 1)) kb[z] = ((h & 1) ? lv.z : lv.x) >> 9;
        }
    }
    // ---- V rows fp16 ----
#pragma unroll
    for (int u = 0; u < 8; u++) {
        int z = warp + 16 * u;
        int t = tfv[u] & (SL - 1);
        float4 vx = ((const float4*)(v + ((size_t)b * SL + t) * D))[lane];
        __half2 v0 = __floats2half2_rn(vx.x, vx.y);
        __half2 v1 = __floats2half2_rn(vx.z, vx.w);
        *(uint2*)(smemc + VHOFF + z * RSB + 8 * lane) =
            make_uint2(*(uint32_t*)&v0, *(uint32_t*)&v1);
    }
    __syncthreads();

    // ---- QK via mma.sync: warp computes S[16 s, 32 z] over k=128 ----
    float acc[4][4];
#pragma unroll
    for (int nt = 0; nt < 4; nt++)
#pragma unroll
        for (int j = 0; j < 4; j++) acc[nt][j] = 0.f;

    uint32_t aQ = smem_u32(smemc) + QHOFF + (16 * sg + (lane & 15)) * RSB + ((lane >> 4) * 8) * 2;
    uint32_t aK = smem_u32(smemc) + KHOFF + (32 * zg + (lane & 7)) * RSB + (((lane >> 3) & 1) * 8) * 2;
#pragma unroll
    for (int k = 0; k < 8; k++) {
        uint32_t a0, a1, a2, a3;
        LDSM_X4(a0, a1, a2, a3, aQ + k * 32);
#pragma unroll
        for (int nt = 0; nt < 4; nt++) {
            uint32_t b0, b1;
            LDSM_X2(b0, b1, aK + nt * 8 * RSB + k * 32);
            MMA16816(acc[nt], a0, a1, a2, a3, b0, b1);
        }
    }

    // ---- masks + dup correction ----
    int s_a = 16 * sg + gid, s_b = s_a + 8;
    int qt_a = qt[s_a], qb_a = qb[s_a], qt_b = qt[s_b], qb_b = qb[s_b];
    int4 qa1 = *(int4*)&ql1[s_a * 8], qa2 = *(int4*)&ql1[s_a * 8 + 4];
    int4 qb1 = *(int4*)&ql1[s_b * 8], qb2 = *(int4*)&ql1[s_b * 8 + 4];
    const float scale = 0.08838834764831845f;
#pragma unroll
    for (int nt = 0; nt < 4; nt++) {
#pragma unroll
        for (int col = 0; col < 2; col++) {
            int z = 32 * zg + 8 * nt + 2 * tig + col;
            int ktv = kt[z], kbv = kb[z];
            int4 ka = *(int4*)&kl[z * 16 + 0];
            int4 kb4 = *(int4*)&kl[z * 16 + 4];
            int4 kc = *(int4*)&kl[z * 16 + 8];
            int4 kd = *(int4*)&kl[z * 16 + 12];
            float va = acc[nt][col] * scale;
            float vb = acc[nt][col + 2] * scale;
            if (qt_a < ktv)  va = MNEG;
            if (qt_a == ktv) va = -10000.f;
            if (qb_a != kbv) va = MNEG;
            if (qt_b < ktv)  vb = MNEG;
            if (qt_b == ktv) vb = -10000.f;
            if (qb_b != kbv) vb = MNEG;
            int ca = 0, cb = 0;
            ca += (qa1.x == ka.x)  + (qa1.x == ka.y);
            ca += (qa1.y == ka.z)  + (qa1.y == ka.w);
            ca += (qa1.z == kb4.x) + (qa1.z == kb4.y);
            ca += (qa1.w == kb4.z) + (qa1.w == kb4.w);
            ca += (qa2.x == kc.x)  + (qa2.x == kc.y);
            ca += (qa2.y == kc.z)  + (qa2.y == kc.w);
            ca += (qa2.z == kd.x)  + (qa2.z == kd.y);
            ca += (qa2.w == kd.z)  + (qa2.w == kd.w);
            cb += (qb1.x == ka.x)  + (qb1.x == ka.y);
            cb += (qb1.y == ka.z)  + (qb1.y == ka.w);
            cb += (qb1.z == kb4.x) + (qb1.z == kb4.y);
            cb += (qb1.w == kb4.z) + (qb1.w == kb4.w);
            cb += (qb2.x == kc.x)  + (qb2.x == kc.y);
            cb += (qb2.y == kc.z)  + (qb2.y == kc.w);
            cb += (qb2.z == kd.x)  + (qb2.z == kd.y);
            cb += (qb2.w == kd.z)  + (qb2.w == kd.w);
            acc[nt][col]     = va - __logf((float)ca + 1e-9f);
            acc[nt][col + 2] = vb - __logf((float)cb + 1e-9f);
        }
    }

    // ---- single-pass local softmax (max + sum at local max), one combine sync ----
    float mxa = MNEG, mxb = MNEG;
#pragma unroll
    for (int nt = 0; nt < 4; nt++) {
        mxa = fmaxf(mxa, fmaxf(acc[nt][0], acc[nt][1]));
        mxb = fmaxf(mxb, fmaxf(acc[nt][2], acc[nt][3]));
    }
#pragma unroll
    for (int o = 1; o <= 2; o <<= 1) {
        mxa = fmaxf(mxa, __shfl_xor_sync(0xffffffffu, mxa, o));
        mxb = fmaxf(mxb, __shfl_xor_sync(0xffffffffu, mxb, o));
    }
    float sa = 0.f, sb = 0.f;
#pragma unroll
    for (int nt = 0; nt < 4; nt++) {
        acc[nt][0] = __expf(acc[nt][0] - mxa);
        acc[nt][1] = __expf(acc[nt][1] - mxa);
        acc[nt][2] = __expf(acc[nt][2] - mxb);
        acc[nt][3] = __expf(acc[nt][3] - mxb);
        sa += acc[nt][0] + acc[nt][1];
        sb += acc[nt][2] + acc[nt][3];
    }
#pragma unroll
    for (int o = 1; o <= 2; o <<= 1) {
        sa += __shfl_xor_sync(0xffffffffu, sa, o);
        sb += __shfl_xor_sync(0xffffffffu, sb, o);
    }
    if (tig == 0) {
        rmax[s_a * 4 + zg] = mxa; rmax[s_b * 4 + zg] = mxb;
        rsum[s_a * 4 + zg] = sa;  rsum[s_b * 4 + zg] = sb;
    }
    __syncthreads();

    float4 ra = *(float4*)&rmax[s_a * 4];
    float4 rb = *(float4*)&rmax[s_b * 4];
    float ma = fmaxf(fmaxf(ra.x, ra.y), fmaxf(ra.z, ra.w));
    float mb = fmaxf(fmaxf(rb.x, rb.y), fmaxf(rb.z, rb.w));
    float4 sra = *(float4*)&rsum[s_a * 4];
    float4 srb = *(float4*)&rsum[s_b * 4];
    float suma = sra.x * __expf(ra.x - ma) + sra.y * __expf(ra.y - ma)
               + sra.z * __expf(ra.z - ma) + sra.w * __expf(ra.w - ma);
    float sumb = srb.x * __expf(rb.x - mb) + srb.y * __expf(rb.y - mb)
               + srb.z * __expf(rb.z - mb) + srb.w * __expf(rb.w - mb);
    float fa = __expf(mxa - ma) / suma;
    float fb = __expf(mxb - mb) / sumb;
#pragma unroll
    for (int nt = 0; nt < 4; nt++) {
        int z0 = 32 * zg + 8 * nt + 2 * tig;
        __half2 pa = __floats2half2_rn(acc[nt][0] * fa, acc[nt][1] * fa);
        __half2 pb = __floats2half2_rn(acc[nt][2] * fb, acc[nt][3] * fb);
        *(__half2*)(smemc + QHOFF + s_a * RSB + z0 * 2) = pa;
        *(__half2*)(smemc + QHOFF + s_b * RSB + z0 * 2) = pb;
    }
    if (zg == 0 && tig == 0) {
        g_slog[b][n * BS + s_a] = ma + __logf(suma);
        g_slog[b][n * BS + s_b] = mb + __logf(sumb);
    }
    __syncthreads();

    // ---- PV via mma.sync: O[16 s, 32 d] = P · V ----
    float o[4][4];
#pragma unroll
    for (int nt = 0; nt < 4; nt++)
#pragma unroll
        for (int j = 0; j < 4; j++) o[nt][j] = 0.f;

    uint32_t aP = smem_u32(smemc) + QHOFF + (16 * sg + (lane & 15)) * RSB + ((lane >> 4) * 8) * 2;
    uint32_t aV = smem_u32(smemc) + VHOFF + (lane & 15) * RSB + (32 * zg) * 2;
#pragma unroll
    for (int k = 0; k < 8; k++) {
        uint32_t a0, a1, a2, a3;
        LDSM_X4(a0, a1, a2, a3, aP + k * 32);
#pragma unroll
        for (int nt = 0; nt < 4; nt++) {
            uint32_t b0, b1;
            LDSM_X2T(b0, b1, aV + k * 16 * RSB + nt * 16);
            MMA16816(o[nt], a0, a1, a2, a3, b0, b1);
        }
    }
#pragma unroll
    for (int nt = 0; nt < 4; nt++) {
        int d0 = 32 * zg + 8 * nt + 2 * tig;
        *(__half2*)&g_so[b][n * BS + s_a][d0] = __floats2half2_rn(o[nt][0], o[nt][1]);
        *(__half2*)&g_so[b][n * BS + s_b][d0] = __floats2half2_rn(o[nt][2], o[nt][3]);
    }
}

__global__ void k_combine(float* __restrict__ out) {
    int t = blockIdx.x, b = blockIdx.y;
    int d = threadIdx.x;
    int p[NH];
    float l[NH];
    float m = MNEG;
#pragma unroll
    for (int h = 0; h < NH; h++) {
        p[h] = g_undo[b][h * SL + t];
        l[h] = g_slog[b][p[h]];
        m = fmaxf(m, l[h]);
    }
    float sum = 0.f;
#pragma unroll
    for (int h = 0; h < NH; h++) { l[h] = __expf(l[h] - m); sum += l[h]; }
    float inv = 1.f / sum;
    float acc = 0.f;
#pragma unroll
    for (int h = 0; h < NH; h++) acc += l[h] * inv * __half2float(g_so[b][p[h]][d]);
    out[((size_t)b * SL + t) * D + d] = acc;
}

extern "C" void kernel_launch(void* const* d_in, const int* in_sizes, int n_in,
                              void* d_out, int out_size) {
    (void)in_sizes; (void)n_in; (void)out_size;
    const float* qk  = (const float*)d_in[0];
    const float* v   = (const float*)d_in[1];
    const float* rot = (const float*)d_in[2];
    float* out = (float*)d_out;

    cudaFuncSetAttribute(k_attn, cudaFuncAttributeMaxDynamicSharedMemorySize, SMEM_ATTN);

    k_zero_hist<<<B, NC>>>();
    k_buckets<<<dim3(SL / 256, NH, B), 256>>>(qk, rot);
    k_prefix<<<B, NC>>>();
    k_scatter<<<dim3(NC, B), 128>>>();
    k_loc<<<(B * SL) / 128, 128>>>();
    k_attn<<<dim3(NC, B), 512, SMEM_ATTN>>>(qk, v);
    k_combine<<<dim3(SL, B), 128>>>(out);
}

// round 15
// speedup vs baseline: 1.7838x; 1.0014x over previous
#include <cuda_runtime.h>
#include <cuda_fp16.h>
#include <stdint.h>
#include <math.h>

#define B 8
#define SL 4096
#define D 128
#define NH 8
#define NB 64
#define NC 512
#define BS 64
#define NSL (NH*SL)
#define MNEG (-3.402823466e38f)

typedef unsigned long long ull;

__device__ __forceinline__ void fma2(ull& d, ull a, ull b) {
    asm("fma.rn.f32x2 %0, %1, %2, %0;" : "+l"(d) : "l"(a), "l"(b));
}
__device__ __forceinline__ ull pack2(float lo, float hi) {
    ull r; asm("mov.b64 %0, {%1, %2};" : "=l"(r) : "f"(lo), "f"(hi)); return r;
}
__device__ __forceinline__ float2 unpack2(ull v) {
    float2 r; asm("mov.b64 {%0, %1}, %2;" : "=f"(r.x), "=f"(r.y) : "l"(v)); return r;
}
__device__ __forceinline__ uint32_t smem_u32(const void* p) {
    uint32_t a;
    asm("{ .reg .u64 t; cvta.to.shared.u64 t, %1; cvt.u32.u64 %0, t; }" : "=r"(a) : "l"(p));
    return a;
}

// ---- warp-level tensor core primitives (portable PTX, HMMA pipe) ----
#define LDSM_X4(r0, r1, r2, r3, a) \
    asm volatile("ldmatrix.sync.aligned.m8n8.x4.shared.b16 {%0,%1,%2,%3}, [%4];" \
        : "=r"(r0), "=r"(r1), "=r"(r2), "=r"(r3) : "r"(a))
#define LDSM_X2(r0, r1, a) \
    asm volatile("ldmatrix.sync.aligned.m8n8.x2.shared.b16 {%0,%1}, [%2];" \
        : "=r"(r0), "=r"(r1) : "r"(a))
#define LDSM_X2T(r0, r1, a) \
    asm volatile("ldmatrix.sync.aligned.m8n8.x2.trans.shared.b16 {%0,%1}, [%2];" \
        : "=r"(r0), "=r"(r1) : "r"(a))
#define MMA16816(c, a0, a1, a2, a3, b0, b1) \
    asm volatile("mma.sync.aligned.m16n8k16.row.col.f32.f16.f16.f32 " \
        "{%0,%1,%2,%3}, {%4,%5,%6,%7}, {%8,%9}, {%0,%1,%2,%3};" \
        : "+f"((c)[0]), "+f"((c)[1]), "+f"((c)[2]), "+f"((c)[3]) \
        : "r"(a0), "r"(a1), "r"(a2), "r"(a3), "r"(b0), "r"(b1))

// ---- k_attn smem layout (bytes). fp16 rows, stride 136 halves = 272 B ----
#define RSB 272
#define QHOFF 0         // Q fp16 64 rows; reused as P fp16
#define KHOFF 17408     // K fp16 128 rows (normalized); reused as V fp16
#define IOFF  52224     // ints: qt64 qb64 kt128 kb128 ql1[512] kl[2048]
#define RMAXOFF 64000   // float[64*4]
#define RSUMOFF 65024   // float[64*4]
#define SMEM_ATTN 66048

// ---------------- scratch ----------------------------------------------------
__device__ int    g_buckets[B][NH][SL];
__device__ int    g_hist[B][NC];
__device__ int    g_boff[B][NC];
__device__ int    g_sticker[B][NSL];
__device__ int    g_undo[B][NSL];
__device__ int    g_locT[B][SL][16];   // interleaved {loc1[h], loc2[h]} pairs
__device__ __half g_so[B][NSL][D];
__device__ float  g_slog[B][NSL];

__global__ void k_zero_hist() { g_hist[blockIdx.x][threadIdx.x] = 0; }

__global__ void k_buckets(const float* __restrict__ qk, const float* __restrict__ rot) {
    __shared__ float rs[32 * 32];
    __shared__ float qt_[256 * 33];
    int b = blockIdx.z, h = blockIdx.y, tid = threadIdx.x;
    int s0 = blockIdx.x * 256;
    ull acc2[16];
#pragma unroll
    for (int n = 0; n < 16; n++) acc2[n] = 0ull;
    for (int d0 = 0; d0 < 128; d0 += 32) {
        for (int i = tid; i < 32 * 32; i += 256) {
            int dd = i >> 5, nn = i & 31;
            rs[i] = rot[((size_t)(d0 + dd) * NH + h) * 32 + nn];
        }
        for (int i = tid; i < 256 * 32; i += 256) {
            int r = i >> 5, c = i & 31;
            qt_[r * 33 + c] = qk[((size_t)b * SL + s0 + r) * D + d0 + c];
        }
        __syncthreads();
#pragma unroll 4
        for (int dd = 0; dd < 32; dd++) {
            float qv = qt_[tid * 33 + dd];
            ull qq = pack2(qv, qv);
            const ull* r2 = (const ull*)&rs[dd * 32];
#pragma unroll
            for (int n = 0; n < 16; n++) fma2(acc2[n], qq, r2[n]);
        }
        __syncthreads();
    }
    float acc[32];
#pragma unroll
    for (int n = 0; n < 16; n++) { float2 p = unpack2(acc2[n]); acc[2*n] = p.x; acc[2*n+1] = p.y; }
    float best = acc[0]; int idx = 0;
#pragma unroll
    for (int n = 1; n < 32; n++) if (acc[n] > best) { best = acc[n]; idx = n; }
#pragma unroll
    for (int n = 0; n < 32; n++) if (-acc[n] > best) { best = -acc[n]; idx = 32 + n; }
    int bucket = idx + h * NB;
    g_buckets[b][h][s0 + tid] = bucket;
    atomicAdd(&g_hist[b][bucket], 1);
}

__global__ void k_prefix() {
    __shared__ int sh[NC];
    int b = blockIdx.x, tid = threadIdx.x;
    int v = g_hist[b][tid];
    sh[tid] = v;
    __syncthreads();
#pragma unroll
    for (int off = 1; off < NC; off <<= 1) {
        int x = (tid >= off) ? sh[tid - off] : 0;
        __syncthreads();
        sh[tid] += x;
        __syncthreads();
    }
    g_boff[b][tid] = sh[tid] - v;
}

__global__ void k_scatter() {
    int bk = blockIdx.x, b = blockIdx.y;
    int h = bk >> 6;
    int warp = threadIdx.x >> 5, lane = threadIdx.x & 31;
    const int* bb = &g_buckets[b][h][0];
    int t0 = warp * (SL / 4);
    __shared__ int wc[4];
    int cnt = 0;
    for (int base = 0; base < SL / 4; base += 32) {
        bool m = (bb[t0 + base + lane] == bk);
        cnt += __popc(__ballot_sync(0xffffffffu, m));
    }
    if (lane == 0) wc[warp] = cnt;
    __syncthreads();
    int pos = g_boff[b][bk];
#pragma unroll
    for (int w = 0; w < 4; w++) if (w < warp) pos += wc[w];
    for (int base = 0; base < SL / 4; base += 32) {
        int t = t0 + base + lane;
        bool m = (bb[t] == bk);
        unsigned bal = __ballot_sync(0xffffffffu, m);
        if (m) {
            int r = __popc(bal & ((1u << lane) - 1));
            int j = h * SL + t;
            g_sticker[b][pos + r] = j;
            g_undo[b][j] = pos + r;
        }
        pos += __popc(bal);
    }
}

// loc codes, transposed layout: thread per (b, t); one 64B coalesced store.
__global__ void k_loc() {
    int idx = blockIdx.x * 128 + threadIdx.x;
    int b = idx >> 12, t = idx & (SL - 1);
    int val[16];
#pragma unroll
    for (int h = 0; h < NH; h++) {
        int bucket = g_buckets[b][h][t];
        int chunk = g_undo[b][h * SL + t] >> 6;
        val[2 * h]     = bucket * NC + chunk;
        val[2 * h + 1] = bucket * NC + ((chunk + 1) & (NC - 1));
    }
    int4* dst = (int4*)&g_locT[b][t][0];
#pragma unroll
    for (int j = 0; j < 4; j++)
        dst[j] = make_int4(val[4 * j], val[4 * j + 1], val[4 * j + 2], val[4 * j + 3]);
}

// Tensor-core attention. grid (NC, B), block 512 (16 warps), 3 blocks/SM.
// One 128-row fp16 buffer holds K during QK, then V during PV.
__global__ void __launch_bounds__(512, 3)
k_attn(const float* __restrict__ qk, const float* __restrict__ v) {
    extern __shared__ char smemc[];
    int n = blockIdx.x, b = blockIdx.y;
    int tid = threadIdx.x, warp = tid >> 5, lane = tid & 31;
    int sg = warp >> 2, zg = warp & 3;
    int gid = lane >> 2, tig = lane & 3;

    int* qt  = (int*)(smemc + IOFF);
    int* qb  = qt + 64;
    int* kt  = qt + 128;
    int* kb  = qt + 256;
    int* ql1 = qt + 384;
    int* kl  = qt + 896;
    float* rmax = (float*)(smemc + RMAXOFF);
    float* rsum = (float*)(smemc + RSUMOFF);

    int prev = (n + NC - 1) & (NC - 1);

    // ---- batched index loads (Q/K only; V indices loaded later) ----
    int tfq[4], tfp[4];
#pragma unroll
    for (int u = 0; u < 4; u++) {
        tfq[u] = g_sticker[b][n * BS + warp + 16 * u];
        tfp[u] = g_sticker[b][prev * BS + warp + 16 * u];
    }

    // ---- current rows: one fp32 load -> Q fp16 (raw) + K fp16 (normalized) ----
#pragma unroll
    for (int u = 0; u < 4; u++) {
        int s = warp + 16 * u;
        int t = tfq[u] & (SL - 1), h = tfq[u] >> 12;
        float4 x = ((const float4*)(qk + ((size_t)b * SL + t) * D))[lane];
        __half2 q0 = __floats2half2_rn(x.x, x.y);
        __half2 q1 = __floats2half2_rn(x.z, x.w);
        *(uint2*)(smemc + QHOFF + s * RSB + 8 * lane) =
            make_uint2(*(uint32_t*)&q0, *(uint32_t*)&q1);
        float ss = x.x * x.x + x.y * x.y + x.z * x.z + x.w * x.w;
#pragma unroll
        for (int o = 16; o > 0; o >>= 1) ss += __shfl_xor_sync(0xffffffffu, ss, o);
        float inv = rsqrtf(fmaxf(ss, 1e-24f));
        __half2 k0 = __floats2half2_rn(x.x * inv, x.y * inv);
        __half2 k1 = __floats2half2_rn(x.z * inv, x.w * inv);
        *(uint2*)(smemc + KHOFF + s * RSB + 8 * lane) =
            make_uint2(*(uint32_t*)&k0, *(uint32_t*)&k1);
        if (lane == 0) { qt[s] = t; kt[s] = t; }
        if (lane < 4) {
            int4 lv = ((const int4*)&g_locT[b][t][0])[lane];
            *(int4*)&kl[s * 16 + 4 * lane] = lv;
            ql1[s * 8 + 2 * lane]     = lv.x;
            ql1[s * 8 + 2 * lane + 1] = lv.z;
            if (lane == (h >> 1)) {
                int bkt = ((h & 1) ? lv.z : lv.x) >> 9;   // loc1 = bucket*512 + chunk
                kb[s] = bkt; qb[s] = bkt;
            }
        }
    }
    // ---- prev rows: K fp16 normalized only (z = 64 + s) ----
#pragma unroll
    for (int u = 0; u < 4; u++) {
        int z = 64 + warp + 16 * u;
        int t = tfp[u] & (SL - 1), h = tfp[u] >> 12;
        float4 x = ((const float4*)(qk + ((size_t)b * SL + t) * D))[lane];
        float ss = x.x * x.x + x.y * x.y + x.z * x.z + x.w * x.w;
#pragma unroll
        for (int o = 16; o > 0; o >>= 1) ss += __shfl_xor_sync(0xffffffffu, ss, o);
        float inv = rsqrtf(fmaxf(ss, 1e-24f));
        __half2 k0 = __floats2half2_rn(x.x * inv, x.y * inv);
        __half2 k1 = __floats2half2_rn(x.z * inv, x.w * inv);
        *(uint2*)(smemc + KHOFF + z * RSB + 8 * lane) =
            make_uint2(*(uint32_t*)&k0, *(uint32_t*)&k1);
        if (lane == 0) kt[z] = t;
        if (lane < 4) {
            int4 lv = ((const int4*)&g_locT[b][t][0])[lane];
            *(int4*)&kl[z * 16 + 4 * lane] = lv;
            if (lane == (h >> 1)) kb[z] = ((h & 1) ? lv.z : lv.x) >> 9;
        }
    }
    __syncthreads();

    // ---- QK via mma.sync: warp computes S[16 s, 32 z] over k=128 ----
    float acc[4][4];
#pragma unroll
    for (int nt = 0; nt < 4; nt++)
#pragma unroll
        for (int j = 0; j < 4; j++) acc[nt][j] = 0.f;

    uint32_t aQ = smem_u32(smemc) + QHOFF + (16 * sg + (lane & 15)) * RSB + ((lane >> 4) * 8) * 2;
    uint32_t aK = smem_u32(smemc) + KHOFF + (32 * zg + (lane & 7)) * RSB + (((lane >> 3) & 1) * 8) * 2;
#pragma unroll
    for (int k = 0; k < 8; k++) {
        uint32_t a0, a1, a2, a3;
        LDSM_X4(a0, a1, a2, a3, aQ + k * 32);
#pragma unroll
        for (int nt = 0; nt < 4; nt++) {
            uint32_t b0, b1;
            LDSM_X2(b0, b1, aK + nt * 8 * RSB + k * 32);
            MMA16816(acc[nt], a0, a1, a2, a3, b0, b1);
        }
    }

    // ---- masks + dup correction ----
    int s_a = 16 * sg + gid, s_b = s_a + 8;
    int qt_a = qt[s_a], qb_a = qb[s_a], qt_b = qt[s_b], qb_b = qb[s_b];
    int4 qa1 = *(int4*)&ql1[s_a * 8], qa2 = *(int4*)&ql1[s_a * 8 + 4];
    int4 qb1 = *(int4*)&ql1[s_b * 8], qb2 = *(int4*)&ql1[s_b * 8 + 4];
    const float scale = 0.08838834764831845f;
#pragma unroll
    for (int nt = 0; nt < 4; nt++) {
#pragma unroll
        for (int col = 0; col < 2; col++) {
            int z = 32 * zg + 8 * nt + 2 * tig + col;
            int ktv = kt[z], kbv = kb[z];
            int4 ka = *(int4*)&kl[z * 16 + 0];
            int4 kb4 = *(int4*)&kl[z * 16 + 4];
            int4 kc = *(int4*)&kl[z * 16 + 8];
            int4 kd = *(int4*)&kl[z * 16 + 12];
            float va = acc[nt][col] * scale;
            float vb = acc[nt][col + 2] * scale;
            if (qt_a < ktv)  va = MNEG;
            if (qt_a == ktv) va = -10000.f;
            if (qb_a != kbv) va = MNEG;
            if (qt_b < ktv)  vb = MNEG;
            if (qt_b == ktv) vb = -10000.f;
            if (qb_b != kbv) vb = MNEG;
            int ca = 0, cb = 0;
            ca += (qa1.x == ka.x)  + (qa1.x == ka.y);
            ca += (qa1.y == ka.z)  + (qa1.y == ka.w);
            ca += (qa1.z == kb4.x) + (qa1.z == kb4.y);
            ca += (qa1.w == kb4.z) + (qa1.w == kb4.w);
            ca += (qa2.x == kc.x)  + (qa2.x == kc.y);
            ca += (qa2.y == kc.z)  + (qa2.y == kc.w);
            ca += (qa2.z == kd.x)  + (qa2.z == kd.y);
            ca += (qa2.w == kd.z)  + (qa2.w == kd.w);
            cb += (qb1.x == ka.x)  + (qb1.x == ka.y);
            cb += (qb1.y == ka.z)  + (qb1.y == ka.w);
            cb += (qb1.z == kb4.x) + (qb1.z == kb4.y);
            cb += (qb1.w == kb4.z) + (qb1.w == kb4.w);
            cb += (qb2.x == kc.x)  + (qb2.x == kc.y);
            cb += (qb2.y == kc.z)  + (qb2.y == kc.w);
            cb += (qb2.z == kd.x)  + (qb2.z == kd.y);
            cb += (qb2.w == kd.z)  + (qb2.w == kd.w);
            acc[nt][col]     = va - __logf((float)ca + 1e-9f);
            acc[nt][col + 2] = vb - __logf((float)cb + 1e-9f);
        }
    }

    // ---- single-pass local softmax; store partials ----
    float mxa = MNEG, mxb = MNEG;
#pragma unroll
    for (int nt = 0; nt < 4; nt++) {
        mxa = fmaxf(mxa, fmaxf(acc[nt][0], acc[nt][1]));
        mxb = fmaxf(mxb, fmaxf(acc[nt][2], acc[nt][3]));
    }
#pragma unroll
    for (int o = 1; o <= 2; o <<= 1) {
        mxa = fmaxf(mxa, __shfl_xor_sync(0xffffffffu, mxa, o));
        mxb = fmaxf(mxb, __shfl_xor_sync(0xffffffffu, mxb, o));
    }
    float sa = 0.f, sb = 0.f;
#pragma unroll
    for (int nt = 0; nt < 4; nt++) {
        acc[nt][0] = __expf(acc[nt][0] - mxa);
        acc[nt][1] = __expf(acc[nt][1] - mxa);
        acc[nt][2] = __expf(acc[nt][2] - mxb);
        acc[nt][3] = __expf(acc[nt][3] - mxb);
        sa += acc[nt][0] + acc[nt][1];
        sb += acc[nt][2] + acc[nt][3];
    }
#pragma unroll
    for (int o = 1; o <= 2; o <<= 1) {
        sa += __shfl_xor_sync(0xffffffffu, sa, o);
        sb += __shfl_xor_sync(0xffffffffu, sb, o);
    }
    if (tig == 0) {
        rmax[s_a * 4 + zg] = mxa; rmax[s_b * 4 + zg] = mxb;
        rsum[s_a * 4 + zg] = sa;  rsum[s_b * 4 + zg] = sb;
    }
    __syncthreads();   // all QK reads of K/Q done; K buffer free, partials visible

    // ---- combine softmax; write P over Q buffer ----
    float4 ra = *(float4*)&rmax[s_a * 4];
    float4 rb = *(float4*)&rmax[s_b * 4];
    float ma = fmaxf(fmaxf(ra.x, ra.y), fmaxf(ra.z, ra.w));
    float mb = fmaxf(fmaxf(rb.x, rb.y), fmaxf(rb.z, rb.w));
    float4 sra = *(float4*)&rsum[s_a * 4];
    float4 srb = *(float4*)&rsum[s_b * 4];
    float suma = sra.x * __expf(ra.x - ma) + sra.y * __expf(ra.y - ma)
               + sra.z * __expf(ra.z - ma) + sra.w * __expf(ra.w - ma);
    float sumb = srb.x * __expf(rb.x - mb) + srb.y * __expf(rb.y - mb)
               + srb.z * __expf(rb.z - mb) + srb.w * __expf(rb.w - mb);
    float fa = __expf(mxa - ma) / suma;
    float fb = __expf(mxb - mb) / sumb;
#pragma unroll
    for (int nt = 0; nt < 4; nt++) {
        int z0 = 32 * zg + 8 * nt + 2 * tig;
        __half2 pa = __floats2half2_rn(acc[nt][0] * fa, acc[nt][1] * fa);
        __half2 pb = __floats2half2_rn(acc[nt][2] * fb, acc[nt][3] * fb);
        *(__half2*)(smemc + QHOFF + s_a * RSB + z0 * 2) = pa;
        *(__half2*)(smemc + QHOFF + s_b * RSB + z0 * 2) = pb;
    }
    if (zg == 0 && tig == 0) {
        g_slog[b][n * BS + s_a] = ma + __logf(suma);
        g_slog[b][n * BS + s_b] = mb + __logf(sumb);
    }

    // ---- V gather into the (freed) K buffer ----
#pragma unroll
    for (int u = 0; u < 8; u++) {
        int z = warp + 16 * u;
        int p = (z < 64) ? (n * BS + z) : (prev * BS + (z - 64));
        int t = g_sticker[b][p] & (SL - 1);
        float4 vx = ((const float4*)(v + ((size_t)b * SL + t) * D))[lane];
        __half2 v0 = __floats2half2_rn(vx.x, vx.y);
        __half2 v1 = __floats2half2_rn(vx.z, vx.w);
        *(uint2*)(smemc + KHOFF + z * RSB + 8 * lane) =
            make_uint2(*(uint32_t*)&v0, *(uint32_t*)&v1);
    }
    __syncthreads();   // P and V visible

    // ---- PV via mma.sync: O[16 s, 32 d] = P · V ----
    float o[4][4];
#pragma unroll
    for (int nt = 0; nt < 4; nt++)
#pragma unroll
        for (int j = 0; j < 4; j++) o[nt][j] = 0.f;

    uint32_t aP = smem_u32(smemc) + QHOFF + (16 * sg + (lane & 15)) * RSB + ((lane >> 4) * 8) * 2;
    uint32_t aV = smem_u32(smemc) + KHOFF + (lane & 15) * RSB + (32 * zg) * 2;
#pragma unroll
    for (int k = 0; k < 8; k++) {
        uint32_t a0, a1, a2, a3;
        LDSM_X4(a0, a1, a2, a3, aP + k * 32);
#pragma unroll
        for (int nt = 0; nt < 4; nt++) {
            uint32_t b0, b1;
            LDSM_X2T(b0, b1, aV + k * 16 * RSB + nt * 16);
            MMA16816(o[nt], a0, a1, a2, a3, b0, b1);
        }
    }
#pragma unroll
    for (int nt = 0; nt < 4; nt++) {
        int d0 = 32 * zg + 8 * nt + 2 * tig;
        *(__half2*)&g_so[b][n * BS + s_a][d0] = __floats2half2_rn(o[nt][0], o[nt][1]);
        *(__half2*)&g_so[b][n * BS + s_b][d0] = __floats2half2_rn(o[nt][2], o[nt][3]);
    }
}

__global__ void k_combine(float* __restrict__ out) {
    int t = blockIdx.x, b = blockIdx.y;
    int d = threadIdx.x;
    int p[NH];
    float l[NH];
    float m = MNEG;
#pragma unroll
    for (int h = 0; h < NH; h++) {
        p[h] = g_undo[b][h * SL + t];
        l[h] = g_slog[b][p[h]];
        m = fmaxf(m, l[h]);
    }
    float sum = 0.f;
#pragma unroll
    for (int h = 0; h < NH; h++) { l[h] = __expf(l[h] - m); sum += l[h]; }
    float inv = 1.f / sum;
    float acc = 0.f;
#pragma unroll
    for (int h = 0; h < NH; h++) acc += l[h] * inv * __half2float(g_so[b][p[h]][d]);
    out[((size_t)b * SL + t) * D + d] = acc;
}

extern "C" void kernel_launch(void* const* d_in, const int* in_sizes, int n_in,
                              void* d_out, int out_size) {
    (void)in_sizes; (void)n_in; (void)out_size;
    const float* qk  = (const float*)d_in[0];
    const float* v   = (const float*)d_in[1];
    const float* rot = (const float*)d_in[2];
    float* out = (float*)d_out;

    cudaFuncSetAttribute(k_attn, cudaFuncAttributeMaxDynamicSharedMemorySize, SMEM_ATTN);

    k_zero_hist<<<B, NC>>>();
    k_buckets<<<dim3(SL / 256, NH, B), 256>>>(qk, rot);
    k_prefix<<<B, NC>>>();
    k_scatter<<<dim3(NC, B), 128>>>();
    k_loc<<<(B * SL) / 128, 128>>>();
    k_attn<<<dim3(NC, B), 512, SMEM_ATTN>>>(qk, v);
    k_combine<<<dim3(SL, B), 128>>>(out);
}